// round 5
// baseline (speedup 1.0000x reference)
#include <cuda_runtime.h>
#include <stdint.h>
#include <math.h>

#define NB 4096

__device__ float g_scratch[336818176];

#define OFF_A1   0u
#define OFF_A2   113639424u
#define OFF_B1   156893184u
#define OFF_B2   256327680u
#define OFF_A3   272547840u
#define OFF_B3   289062912u
#define OFF_AL   291127296u
#define OFF_BL   303710208u
#define OFF_G    310001664u
#define OFF_ZA   318390272u
#define OFF_ZB   325074944u
#define OFF_Z1   331759616u
#define OFF_BD1  334905344u
#define OFF_BDO  335323136u
#define OFF_BH   336158720u
#define OFF_LOG  336551936u
#define OFF_ENT  336814080u

__device__ __forceinline__ uint32_t smem_u32(const void* p) {
    uint32_t a;
    asm("{ .reg .u64 t; cvta.to.shared.u64 t, %1; cvt.u32.u64 %0, t; }" : "=r"(a) : "l"(p));
    return a;
}
__device__ __forceinline__ float tf32r(float x) {
    uint32_t u; asm("cvt.rna.tf32.f32 %0, %1;" : "=r"(u) : "f"(x)); return __uint_as_float(u);
}

// ---------- threefry (JAX partitionable) ----------
__host__ __device__ __forceinline__ void threefry2x32(
    uint32_t k0, uint32_t k1, uint32_t x0, uint32_t x1, uint32_t* o0, uint32_t* o1)
{
    uint32_t ks0 = k0, ks1 = k1, ks2 = 0x1BD11BDAu ^ k0 ^ k1;
    x0 += ks0; x1 += ks1;
#define TF_ROUND(r) do { x0 += x1; x1 = (x1 << (r)) | (x1 >> (32 - (r))); x1 ^= x0; } while (0)
    TF_ROUND(13); TF_ROUND(15); TF_ROUND(26); TF_ROUND(6);
    x0 += ks1; x1 += ks2 + 1u;
    TF_ROUND(17); TF_ROUND(29); TF_ROUND(16); TF_ROUND(24);
    x0 += ks2; x1 += ks0 + 2u;
    TF_ROUND(13); TF_ROUND(15); TF_ROUND(26); TF_ROUND(6);
    x0 += ks0; x1 += ks1 + 3u;
    TF_ROUND(17); TF_ROUND(29); TF_ROUND(16); TF_ROUND(24);
    x0 += ks1; x1 += ks2 + 4u;
    TF_ROUND(13); TF_ROUND(15); TF_ROUND(26); TF_ROUND(6);
    x0 += ks2; x1 += ks0 + 5u;
#undef TF_ROUND
    *o0 = x0; *o1 = x1;
}
__device__ __forceinline__ float gumbel_for(uint32_t k0, uint32_t k1, uint32_t j)
{
    uint32_t o0, o1;
    threefry2x32(k0, k1, 0u, j, &o0, &o1);
    uint32_t bits = o0 ^ o1;
    uint32_t fb = (bits >> 9) | 0x3f800000u;
    float f = __uint_as_float(fb) - 1.0f;
    if (f == 0.0f) f = 1.1754943508222875e-38f;
    return -logf(-logf(f));
}

__device__ __forceinline__ void mma_tf32(float* c, const uint32_t* a, const uint32_t* b)
{
    asm volatile(
        "mma.sync.aligned.m16n8k8.row.col.f32.tf32.tf32.f32 "
        "{%0,%1,%2,%3}, {%4,%5,%6,%7}, {%8,%9}, {%0,%1,%2,%3};"
        : "+f"(c[0]), "+f"(c[1]), "+f"(c[2]), "+f"(c[3])
        : "r"(a[0]), "r"(a[1]), "r"(a[2]), "r"(a[3]), "r"(b[0]), "r"(b[1]));
}

// ==================================================================
// BIG tf32 GEMM: 128x256 tile, 512 threads, 3-stage cp.async
// ==================================================================
__global__ void __launch_bounds__(512, 1)
mma_big(const float* __restrict__ A, int lda,
        const float* __restrict__ B, int ldb, int Brows, int Kp,
        const float* __restrict__ bias, const float* __restrict__ bias2,
        float* __restrict__ out, int ldOut, int sec,
        int Nreal, int NpadStore, int relu)
{
    extern __shared__ float sm[];
    const int tid  = threadIdx.x;
    const int bm   = blockIdx.y * 128;
    const int bn   = blockIdx.x * 256;
    const int lane = tid & 31;
    const int wid  = tid >> 5;
    const int wm   = wid >> 3;   // 0..1 (64 rows)
    const int wn   = wid & 7;    // 0..7 (32 cols)

    // stage: A 128x36 (4608 fl) + B 256x36 (9216 fl) = 13824 fl = 55296 B
    const uint32_t aBase = smem_u32(sm);

    float acc[4][4][4];
#pragma unroll
    for (int i = 0; i < 4; i++)
#pragma unroll
        for (int j = 0; j < 4; j++)
#pragma unroll
            for (int e = 0; e < 4; e++) acc[i][j][e] = 0.0f;

    const int niter = Kp >> 5;

#define LOAD_TILE_B(buf, kt) do {                                             \
    int _k0 = (kt) * 32;                                                      \
    _Pragma("unroll")                                                         \
    for (int _i = 0; _i < 2; _i++) {                                          \
        int _idx = tid + _i * 512;                                            \
        int _row = _idx >> 3, _cj = _idx & 7;                                 \
        uint32_t _da = aBase + (buf) * 55296u + _row * 144u + _cj * 16u;      \
        const float* _ga = A + (size_t)(bm + _row) * lda + _k0 + _cj * 4;     \
        asm volatile("cp.async.cg.shared.global [%0], [%1], 16;"              \
                     :: "r"(_da), "l"(_ga));                                  \
    }                                                                         \
    _Pragma("unroll")                                                         \
    for (int _i = 0; _i < 4; _i++) {                                          \
        int _idx = tid + _i * 512;                                            \
        int _row = _idx >> 3, _cj = _idx & 7;                                 \
        uint32_t _db = aBase + (buf) * 55296u + 18432u + _row * 144u + _cj * 16u; \
        int _ok = (bn + _row < Brows);                                        \
        const float* _gb = _ok ? (B + (size_t)(bn + _row) * ldb + _k0 + _cj * 4) : B; \
        int _sz = _ok ? 16 : 0;                                               \
        asm volatile("cp.async.cg.shared.global [%0], [%1], 16, %2;"          \
                     :: "r"(_db), "l"(_gb), "r"(_sz));                        \
    }                                                                         \
    asm volatile("cp.async.commit_group;" ::: "memory");                      \
} while (0)

    LOAD_TILE_B(0, 0);
    if (niter > 1) LOAD_TILE_B(1, 1);

    for (int kt = 0; kt < niter; kt++) {
        if (kt + 1 < niter)
            asm volatile("cp.async.wait_group 1;" ::: "memory");
        else
            asm volatile("cp.async.wait_group 0;" ::: "memory");
        __syncthreads();

        const int buf = kt % 3;
        if (kt + 2 < niter) LOAD_TILE_B((kt + 2) % 3, kt + 2);

        const float* as = sm + buf * 13824;
        const float* bs = as + 4608;
#pragma unroll
        for (int ks = 0; ks < 4; ks++) {
            uint32_t a[4][4], b[4][2];
            const int r0 = wm * 64 + (lane >> 2);
            const int c0 = ks * 8 + (lane & 3);
#pragma unroll
            for (int mi = 0; mi < 4; mi++) {
                a[mi][0] = __float_as_uint(as[(r0 + mi * 16) * 36 + c0]);
                a[mi][1] = __float_as_uint(as[(r0 + mi * 16 + 8) * 36 + c0]);
                a[mi][2] = __float_as_uint(as[(r0 + mi * 16) * 36 + c0 + 4]);
                a[mi][3] = __float_as_uint(as[(r0 + mi * 16 + 8) * 36 + c0 + 4]);
            }
            const int n0 = wn * 32 + (lane >> 2);
#pragma unroll
            for (int ni = 0; ni < 4; ni++) {
                b[ni][0] = __float_as_uint(bs[(n0 + ni * 8) * 36 + c0]);
                b[ni][1] = __float_as_uint(bs[(n0 + ni * 8) * 36 + c0 + 4]);
            }
#pragma unroll
            for (int mi = 0; mi < 4; mi++)
#pragma unroll
                for (int ni = 0; ni < 4; ni++)
                    mma_tf32(acc[mi][ni], a[mi], b[ni]);
        }
        __syncthreads();
    }
#undef LOAD_TILE_B

#pragma unroll
    for (int mi = 0; mi < 4; mi++)
#pragma unroll
        for (int ni = 0; ni < 4; ni++)
#pragma unroll
            for (int e = 0; e < 4; e++) {
                int m = bm + wm * 64 + mi * 16 + (lane >> 2) + ((e >= 2) ? 8 : 0);
                int n = bn + wn * 32 + ni * 8 + 2 * (lane & 3) + (e & 1);
                float v = 0.0f;
                if (n < Nreal) {
                    v = acc[mi][ni][e];
                    if (bias)  v += bias[n];
                    if (bias2) v += bias2[n];
                    if (relu)  v = fmaxf(v, 0.0f);
                }
                if (sec == 0) {
                    if (n < Nreal) out[(size_t)m * ldOut + n] = v;
                } else if (n < NpadStore) {
                    float hi = tf32r(v);
                    float* p = out + (size_t)m * ldOut;
                    p[n] = hi; p[sec + n] = v - hi; p[2 * sec + n] = hi;
                }
            }
}

// ==================================================================
// small tf32 GEMM: 128x128 tile, 256 threads, 2-stage (decoder)
// ==================================================================
__global__ void __launch_bounds__(256, 2)
mma_gemm(const float* __restrict__ A, int lda,
         const float* __restrict__ B, int ldb, int Brows, int Kp,
         const float* __restrict__ bias, const float* __restrict__ bias2,
         float* __restrict__ out, int ldOut, int sec,
         int Nreal, int NpadStore, int relu)
{
    extern __shared__ float sm[];
    const int tid  = threadIdx.x;
    const int bm   = blockIdx.y * 128;
    const int bn   = blockIdx.x * 128;
    const int lane = tid & 31;
    const int wid  = tid >> 5;
    const int wm   = wid >> 2;
    const int wn   = wid & 3;

    const uint32_t aBase = smem_u32(sm);
    const uint32_t bBase = aBase + 2u * 18432u;

    float acc[4][4][4];
#pragma unroll
    for (int i = 0; i < 4; i++)
#pragma unroll
        for (int j = 0; j < 4; j++)
#pragma unroll
            for (int e = 0; e < 4; e++) acc[i][j][e] = 0.0f;

    const int niter = Kp >> 5;

#define LOAD_TILE(buf, kt) do {                                               \
    int _k0 = (kt) * 32;                                                      \
    _Pragma("unroll")                                                         \
    for (int _i = 0; _i < 4; _i++) {                                          \
        int _idx = tid + _i * 256;                                            \
        int _row = _idx >> 3, _cj = _idx & 7;                                 \
        uint32_t _da = aBase + (buf) * 18432u + _row * 144u + _cj * 16u;      \
        const float* _ga = A + (size_t)(bm + _row) * lda + _k0 + _cj * 4;     \
        asm volatile("cp.async.cg.shared.global [%0], [%1], 16;"              \
                     :: "r"(_da), "l"(_ga));                                  \
        uint32_t _db = bBase + (buf) * 18432u + _row * 144u + _cj * 16u;      \
        int _ok = (bn + _row < Brows);                                        \
        const float* _gb = _ok ? (B + (size_t)(bn + _row) * ldb + _k0 + _cj * 4) : B; \
        int _sz = _ok ? 16 : 0;                                               \
        asm volatile("cp.async.cg.shared.global [%0], [%1], 16, %2;"          \
                     :: "r"(_db), "l"(_gb), "r"(_sz));                        \
    }                                                                         \
    asm volatile("cp.async.commit_group;" ::: "memory");                      \
} while (0)

    LOAD_TILE(0, 0);

    for (int kt = 0; kt < niter; kt++) {
        const int buf = kt & 1;
        if (kt + 1 < niter) {
            LOAD_TILE(buf ^ 1, kt + 1);
            asm volatile("cp.async.wait_group 1;" ::: "memory");
        } else {
            asm volatile("cp.async.wait_group 0;" ::: "memory");
        }
        __syncthreads();

        const float* as = sm + buf * 4608;
        const float* bs = sm + 2 * 4608 + buf * 4608;
#pragma unroll
        for (int ks = 0; ks < 4; ks++) {
            uint32_t a[4][4], b[4][2];
            const int r0 = wm * 64 + (lane >> 2);
            const int c0 = ks * 8 + (lane & 3);
#pragma unroll
            for (int mi = 0; mi < 4; mi++) {
                a[mi][0] = __float_as_uint(as[(r0 + mi * 16) * 36 + c0]);
                a[mi][1] = __float_as_uint(as[(r0 + mi * 16 + 8) * 36 + c0]);
                a[mi][2] = __float_as_uint(as[(r0 + mi * 16) * 36 + c0 + 4]);
                a[mi][3] = __float_as_uint(as[(r0 + mi * 16 + 8) * 36 + c0 + 4]);
            }
            const int n0 = wn * 32 + (lane >> 2);
#pragma unroll
            for (int ni = 0; ni < 4; ni++) {
                b[ni][0] = __float_as_uint(bs[(n0 + ni * 8) * 36 + c0]);
                b[ni][1] = __float_as_uint(bs[(n0 + ni * 8) * 36 + c0 + 4]);
            }
#pragma unroll
            for (int mi = 0; mi < 4; mi++)
#pragma unroll
                for (int ni = 0; ni < 4; ni++)
                    mma_tf32(acc[mi][ni], a[mi], b[ni]);
        }
        __syncthreads();
    }
#undef LOAD_TILE

#pragma unroll
    for (int mi = 0; mi < 4; mi++)
#pragma unroll
        for (int ni = 0; ni < 4; ni++)
#pragma unroll
            for (int e = 0; e < 4; e++) {
                int m = bm + wm * 64 + mi * 16 + (lane >> 2) + ((e >= 2) ? 8 : 0);
                int n = bn + wn * 32 + ni * 8 + 2 * (lane & 3) + (e & 1);
                float v = 0.0f;
                if (n < Nreal) {
                    v = acc[mi][ni][e];
                    if (bias)  v += bias[n];
                    if (bias2) v += bias2[n];
                    if (relu)  v = fmaxf(v, 0.0f);
                }
                if (sec == 0) {
                    if (n < Nreal) out[(size_t)m * ldOut + n] = v;
                } else if (n < NpadStore) {
                    float hi = tf32r(v);
                    float* p = out + (size_t)m * ldOut;
                    p[n] = hi; p[sec + n] = v - hi; p[2 * sec + n] = hi;
                }
            }
}

// ---------- prep kernels ----------
__global__ void build_A1(const float* __restrict__ s0, const float* __restrict__ s1,
                         const float* __restrict__ s2, const int* __restrict__ epPtr,
                         float* __restrict__ A1)
{
    int k = blockIdx.x * 256 + threadIdx.x;
    int m = blockIdx.y;
    if (k >= 9248) return;
    float v = 0.0f;
    if (k < 4608)       v = s0[(size_t)m * 4608 + k];
    else if (k < 9216)  v = s1[(size_t)m * 4608 + (k - 4608)];
    else if (k < 9224)  v = s2[m * 8 + (k - 9216)];
    else if (k == 9224) v = epPtr ? (float)(*epPtr) : 0.0f;
    float hi = tf32r(v);
    size_t b = (size_t)m * 27744;
    A1[b + k] = hi; A1[b + 9248 + k] = v - hi; A1[b + 18496 + k] = hi;
}

__global__ void tsplit(const float* __restrict__ W, int K, int N,
                       float* __restrict__ out, int Kpad)
{
    __shared__ float t[32][33];
    int kb = blockIdx.x * 32, nb = blockIdx.y * 32;
    int tx = threadIdx.x, ty = threadIdx.y;
#pragma unroll
    for (int r = 0; r < 4; r++) {
        int k = kb + ty + r * 8, n = nb + tx;
        t[ty + r * 8][tx] = (k < K && n < N) ? W[(size_t)k * N + n] : 0.0f;
    }
    __syncthreads();
#pragma unroll
    for (int r = 0; r < 4; r++) {
        int n = nb + ty + r * 8, k = kb + tx;
        float v = t[tx][ty + r * 8];
        float hi = tf32r(v);
        size_t b = (size_t)n * (3 * (size_t)Kpad);
        out[b + k] = hi; out[b + Kpad + k] = hi; out[b + 2 * Kpad + k] = v - hi;
    }
}

__global__ void split_lstm(const float* __restrict__ Wih, const float* __restrict__ Whh,
                           float* __restrict__ out)
{
    int idx = blockIdx.x * 256 + threadIdx.x;
    if (idx >= 2048 * 512) return;
    int n = idx >> 9, k = idx & 511;
    float a = Wih[idx], c = Whh[idx];
    float ah = tf32r(a), ch = tf32r(c);
    size_t b = (size_t)n * 3072;
    out[b + k] = ah;            out[b + 512 + k] = ch;
    out[b + 1024 + k] = ah;     out[b + 1536 + k] = ch;
    out[b + 2048 + k] = a - ah; out[b + 2560 + k] = c - ch;
}

__global__ void h0split(const float* __restrict__ h0, float* __restrict__ AL)
{
    int idx = blockIdx.x * 256 + threadIdx.x;
    if (idx >= NB * 512) return;
    int m = idx >> 9, c = idx & 511;
    float v = h0[idx];
    float hi = tf32r(v);
    size_t b = (size_t)m * 3072;
    AL[b + 512 + c] = hi; AL[b + 1536 + c] = v - hi; AL[b + 2560 + c] = hi;
}

__global__ void lstm_kernel(const float* __restrict__ gates,
                            const float* __restrict__ c0, float* __restrict__ za)
{
    int i = blockIdx.x * blockDim.x + threadIdx.x;
    if (i >= NB * 512) return;
    int m = i >> 9, c = i & 511;
    const float* gr = gates + (size_t)m * 2048;
    float gi = gr[c], gf = gr[512 + c], gg = gr[1024 + c], go = gr[1536 + c];
    float si = 1.0f / (1.0f + expf(-gi));
    float sf = 1.0f / (1.0f + expf(-gf));
    float so = 1.0f / (1.0f + expf(-go));
    float cc = sf * c0[i] + si * tanhf(gg);
    float z = so * tanhf(cc);
    float hi = tf32r(z);
    size_t b = (size_t)m * 1632;
    za[b + c] = hi; za[b + 544 + c] = z - hi; za[b + 1088 + c] = hi;
}

__global__ void sample_kernel(const float* __restrict__ logits,
                              float* __restrict__ zin,
                              float* __restrict__ outAction,
                              float* __restrict__ lpAcc,
                              float* __restrict__ entAcc,
                              uint32_t sk0, uint32_t sk1, int head)
{
    int warp = (blockIdx.x * blockDim.x + threadIdx.x) >> 5;
    int lane = threadIdx.x & 31;
    if (warp >= NB) return;
    int r = warp;

    float x0 = logits[r * 64 + lane];
    float x1 = logits[r * 64 + 32 + lane];

    float mx = fmaxf(x0, x1);
#pragma unroll
    for (int o = 16; o; o >>= 1) mx = fmaxf(mx, __shfl_xor_sync(0xffffffffu, mx, o));
    float s = expf(x0 - mx) + expf(x1 - mx);
#pragma unroll
    for (int o = 16; o; o >>= 1) s += __shfl_xor_sync(0xffffffffu, s, o);
    float lse = mx + logf(s);

    float t = expf(x0 - lse) * (lse - x0) + expf(x1 - lse) * (lse - x1);
#pragma unroll
    for (int o = 16; o; o >>= 1) t += __shfl_xor_sync(0xffffffffu, t, o);

    float g0 = gumbel_for(sk0, sk1, (uint32_t)(r * 64 + lane));
    float g1 = gumbel_for(sk0, sk1, (uint32_t)(r * 64 + 32 + lane));
    float ya = x0 + g0, yb = x1 + g1;
    float y; int idx;
    if (ya >= yb) { y = ya; idx = lane; } else { y = yb; idx = lane + 32; }
#pragma unroll
    for (int o = 16; o; o >>= 1) {
        float oy = __shfl_xor_sync(0xffffffffu, y, o);
        int   oi = __shfl_xor_sync(0xffffffffu, idx, o);
        if (oy > y || (oy == y && oi < idx)) { y = oy; idx = oi; }
    }
    int src = idx & 31;
    float v0 = __shfl_sync(0xffffffffu, x0, src);
    float v1 = __shfl_sync(0xffffffffu, x1, src);
    float xw = (idx < 32) ? v0 : v1;

    if (lane == 0) {
        float a = (float)idx;
        size_t b = (size_t)r * 1632;
        zin[b + 512] = a;
        zin[b + 544 + 512] = 0.0f;
        zin[b + 1088 + 512] = a;
        outAction[r * 8 + head] = a;
        lpAcc[r] += xw - lse;
        entAcc[r] += t;
    }
}

__global__ void init_kernel(float* __restrict__ lp, float* __restrict__ ent)
{
    int i = blockIdx.x * blockDim.x + threadIdx.x;
    if (i < NB) { lp[i] = 0.0f; ent[i] = 0.0f; }
}

__global__ void reduce_ent(const float* __restrict__ ent, float* __restrict__ out)
{
    __shared__ float sm[256];
    float s = 0.0f;
    for (int i = threadIdx.x; i < NB; i += 256) s += ent[i];
    sm[threadIdx.x] = s;
    __syncthreads();
    for (int o = 128; o; o >>= 1) {
        if (threadIdx.x < o) sm[threadIdx.x] += sm[threadIdx.x + o];
        __syncthreads();
    }
    if (threadIdx.x == 0) out[0] = sm[0];
}

// ---------- host launcher ----------
extern "C" void kernel_launch(void* const* d_in, const int* in_sizes, int n_in,
                              void* d_out, int out_size)
{
    const float* actual    = (const float*)d_in[0];
    const float* objective = (const float*)d_in[1];
    const float* last      = (const float*)d_in[2];

    int base = 4;
    const int* epPtr = nullptr;
    if (in_sizes[3] == 1) epPtr = (const int*)d_in[3];
    else base = 3;

    const float* W1  = (const float*)d_in[base + 0];
    const float* b1  = (const float*)d_in[base + 1];
    const float* W2  = (const float*)d_in[base + 2];
    const float* b2  = (const float*)d_in[base + 3];
    const float* W3  = (const float*)d_in[base + 4];
    const float* b3  = (const float*)d_in[base + 5];
    const float* Wih = (const float*)d_in[base + 6];
    const float* Whh = (const float*)d_in[base + 7];
    const float* bih = (const float*)d_in[base + 8];
    const float* bhh = (const float*)d_in[base + 9];
    const float* h0  = (const float*)d_in[base + 10];
    const float* c0  = (const float*)d_in[base + 11];
    const float* dW1 = (const float*)d_in[base + 12];
    const float* db1 = (const float*)d_in[base + 13];

    const float* headW[8];
    const float* headb[8];
    const float* dWo;
    const float* dbo;
    if (n_in >= base + 32) {
        for (int i = 0; i < 8; i++) {
            headW[i] = (const float*)d_in[base + 14 + i];
            headb[i] = (const float*)d_in[base + 22 + i];
        }
        dWo = (const float*)d_in[base + 30];
        dbo = (const float*)d_in[base + 31];
    } else {
        const float* hw = (const float*)d_in[base + 14];
        const float* hb = (const float*)d_in[base + 15];
        for (int i = 0; i < 8; i++) {
            headW[i] = hw + (size_t)i * 256 * 64;
            headb[i] = hb + (size_t)i * 64;
        }
        dWo = (const float*)d_in[base + 16];
        dbo = (const float*)d_in[base + 17];
    }
    const int D1 = in_sizes[base + 1];  // 3518
    const int D2 = in_sizes[base + 3];  // 1342

    float* sc = nullptr;
    cudaGetSymbolAddress((void**)&sc, g_scratch);
    float* A1 = sc + OFF_A1;   float* A2 = sc + OFF_A2;
    float* B1 = sc + OFF_B1;   float* B2 = sc + OFF_B2;
    float* A3 = sc + OFF_A3;   float* B3 = sc + OFF_B3;
    float* AL = sc + OFF_AL;   float* BL = sc + OFF_BL;
    float* gates = sc + OFF_G;
    float* za = sc + OFF_ZA;   float* zb = sc + OFF_ZB;
    float* Z1 = sc + OFF_Z1;
    float* BD1 = sc + OFF_BD1; float* BDO = sc + OFF_BDO;
    float* BH = sc + OFF_BH;
    float* logb = sc + OFF_LOG;
    float* entb = sc + OFF_ENT;

    float* out  = (float*)d_out;
    float* lp   = out + NB * 8 + 1;
    float* entO = out + NB * 8;

    uint32_t k0 = 0u, k1 = 42u, sk0[8], sk1[8];
    for (int t = 0; t < 8; t++) {
        uint32_t n0, n1, s0, s1;
        threefry2x32(k0, k1, 0u, 0u, &n0, &n1);
        threefry2x32(k0, k1, 0u, 1u, &s0, &s1);
        sk0[t] = s0; sk1[t] = s1;
        k0 = n0; k1 = n1;
    }

    const int SMEM  = 4 * 18432;    // small kernel: 73728 B
    const int SMEMB = 3 * 55296;    // big kernel: 165888 B
    cudaFuncSetAttribute(mma_gemm, cudaFuncAttributeMaxDynamicSharedMemorySize, SMEM);
    cudaFuncSetAttribute(mma_big,  cudaFuncAttributeMaxDynamicSharedMemorySize, SMEMB);

    dim3 blk(256);
    dim3 blkB(512);
    dim3 tsb(32, 8);

    init_kernel<<<(NB + 255) / 256, blk>>>(lp, entb);

    // weight prep
    tsplit<<<dim3(289, 112), tsb>>>(W1, 9225, D1, B1, 9248);
    tsplit<<<dim3(110, 48),  tsb>>>(W2, D1, D2, B2, 3520);
    tsplit<<<dim3(42, 16),   tsb>>>(W3, D2, 512, B3, 1344);
    split_lstm<<<(2048 * 512 + 255) / 256, blk>>>(Wih, Whh, BL);
    h0split<<<(NB * 512 + 255) / 256, blk>>>(h0, AL);
    tsplit<<<dim3(17, 8),  tsb>>>(dW1, 512, 256, BD1, 544);
    tsplit<<<dim3(17, 16), tsb>>>(dWo, 513, 512, BDO, 544);
    for (int t = 0; t < 8; t++)
        tsplit<<<dim3(8, 2), tsb>>>(headW[t], 256, 64, BH + (size_t)t * 49152, 256);
    build_A1<<<dim3(37, 4096), blk>>>(actual, objective, last, epPtr, A1);

    // encoder (big tiles)
    mma_big<<<dim3(14, 32), blkB, SMEMB>>>(A1, 27744, B1, 27744, 3520, 27744,
        b1, nullptr, A2, 10560, 3520, D1, 3520, 1);
    mma_big<<<dim3(6, 32), blkB, SMEMB>>>(A2, 10560, B2, 10560, 1344, 10560,
        b2, nullptr, A3, 4032, 1344, D2, 1344, 1);
    mma_big<<<dim3(2, 32), blkB, SMEMB>>>(A3, 4032, B3, 4032, 512, 4032,
        b3, nullptr, AL, 3072, 1024, 512, 512, 1);

    // LSTM (big tiles)
    mma_big<<<dim3(8, 32), blkB, SMEMB>>>(AL, 3072, BL, 3072, 2048, 3072,
        bih, bhh, gates, 2048, 0, 2048, 0, 0);
    lstm_kernel<<<(NB * 512 + 255) / 256, blk>>>(gates, c0, za);

    // decoder (small tiles)
    for (int t = 0; t < 8; t++) {
        float* zin  = (t & 1) ? zb : za;
        float* zout = (t & 1) ? za : zb;
        mma_gemm<<<dim3(2, 32), blk, SMEM>>>(zin, 1632, BD1, 1632, 256, 1632,
            db1, nullptr, Z1, 768, 256, 256, 256, 1);
        mma_gemm<<<dim3(1, 32), blk, SMEM>>>(Z1, 768, BH + (size_t)t * 49152, 768, 64, 768,
            headb[t], nullptr, logb, 64, 0, 64, 0, 0);
        sample_kernel<<<NB / 8, blk>>>(logb, zin, out, lp, entb, sk0[t], sk1[t], t);
        mma_gemm<<<dim3(4, 32), blk, SMEM>>>(zin, 1632, BDO, 1632, 512, 1632,
            dbo, nullptr, zout, 1632, 544, 512, 512, 1);
    }

    reduce_ent<<<1, blk>>>(entb, entO);
}

// round 6
// speedup vs baseline: 1.1265x; 1.1265x over previous
#include <cuda_runtime.h>
#include <stdint.h>
#include <math.h>

#define NB 4096

__device__ float g_scratch[336818176];

#define OFF_A1   0u
#define OFF_A2   113639424u
#define OFF_B1   156893184u
#define OFF_B2   256327680u
#define OFF_A3   272547840u
#define OFF_B3   289062912u
#define OFF_AL   291127296u
#define OFF_BL   303710208u
#define OFF_G    310001664u
#define OFF_ZA   318390272u
#define OFF_ZB   325074944u
#define OFF_Z1   331759616u
#define OFF_BD1  334905344u
#define OFF_BDO  335323136u
#define OFF_BH   336158720u
#define OFF_LOG  336551936u
#define OFF_ENT  336814080u

__device__ __forceinline__ uint32_t smem_u32(const void* p) {
    uint32_t a;
    asm("{ .reg .u64 t; cvta.to.shared.u64 t, %1; cvt.u32.u64 %0, t; }" : "=r"(a) : "l"(p));
    return a;
}
__device__ __forceinline__ float tf32r(float x) {
    uint32_t u; asm("cvt.rna.tf32.f32 %0, %1;" : "=r"(u) : "f"(x)); return __uint_as_float(u);
}

// ---------- threefry (JAX partitionable) ----------
__host__ __device__ __forceinline__ void threefry2x32(
    uint32_t k0, uint32_t k1, uint32_t x0, uint32_t x1, uint32_t* o0, uint32_t* o1)
{
    uint32_t ks0 = k0, ks1 = k1, ks2 = 0x1BD11BDAu ^ k0 ^ k1;
    x0 += ks0; x1 += ks1;
#define TF_ROUND(r) do { x0 += x1; x1 = (x1 << (r)) | (x1 >> (32 - (r))); x1 ^= x0; } while (0)
    TF_ROUND(13); TF_ROUND(15); TF_ROUND(26); TF_ROUND(6);
    x0 += ks1; x1 += ks2 + 1u;
    TF_ROUND(17); TF_ROUND(29); TF_ROUND(16); TF_ROUND(24);
    x0 += ks2; x1 += ks0 + 2u;
    TF_ROUND(13); TF_ROUND(15); TF_ROUND(26); TF_ROUND(6);
    x0 += ks0; x1 += ks1 + 3u;
    TF_ROUND(17); TF_ROUND(29); TF_ROUND(16); TF_ROUND(24);
    x0 += ks1; x1 += ks2 + 4u;
    TF_ROUND(13); TF_ROUND(15); TF_ROUND(26); TF_ROUND(6);
    x0 += ks2; x1 += ks0 + 5u;
#undef TF_ROUND
    *o0 = x0; *o1 = x1;
}
__device__ __forceinline__ float gumbel_for(uint32_t k0, uint32_t k1, uint32_t j)
{
    uint32_t o0, o1;
    threefry2x32(k0, k1, 0u, j, &o0, &o1);
    uint32_t bits = o0 ^ o1;
    uint32_t fb = (bits >> 9) | 0x3f800000u;
    float f = __uint_as_float(fb) - 1.0f;
    if (f == 0.0f) f = 1.1754943508222875e-38f;
    return -logf(-logf(f));
}

__device__ __forceinline__ void mma_tf32(float* c, const uint32_t* a, const uint32_t* b)
{
    asm volatile(
        "mma.sync.aligned.m16n8k8.row.col.f32.tf32.tf32.f32 "
        "{%0,%1,%2,%3}, {%4,%5,%6,%7}, {%8,%9}, {%0,%1,%2,%3};"
        : "+f"(c[0]), "+f"(c[1]), "+f"(c[2]), "+f"(c[3])
        : "r"(a[0]), "r"(a[1]), "r"(a[2]), "r"(a[3]), "r"(b[0]), "r"(b[1]));
}

// ==================================================================
// tf32 mma.sync GEMM: 128x128 tile, 256 threads, 3-stage cp.async,
// single __syncthreads per k-iter, 2 CTAs/SM.
// stage: A 128x36 + B 128x36 = 9216 floats = 36864 B; 3 stages = 110592 B
// ==================================================================
__global__ void __launch_bounds__(256, 2)
mma_gemm(const float* __restrict__ A, int lda,
         const float* __restrict__ B, int ldb, int Brows, int Kp,
         const float* __restrict__ bias, const float* __restrict__ bias2,
         float* __restrict__ out, int ldOut, int sec,
         int Nreal, int NpadStore, int relu)
{
    extern __shared__ float sm[];
    const int tid  = threadIdx.x;
    const int bm   = blockIdx.y * 128;
    const int bn   = blockIdx.x * 128;
    const int lane = tid & 31;
    const int wid  = tid >> 5;
    const int wm   = wid >> 2;
    const int wn   = wid & 3;

    const uint32_t aBase = smem_u32(sm);

    float acc[4][4][4];
#pragma unroll
    for (int i = 0; i < 4; i++)
#pragma unroll
        for (int j = 0; j < 4; j++)
#pragma unroll
            for (int e = 0; e < 4; e++) acc[i][j][e] = 0.0f;

    const int niter = Kp >> 5;

#define LOAD_TILE(buf, kt) do {                                               \
    int _k0 = (kt) * 32;                                                      \
    _Pragma("unroll")                                                         \
    for (int _i = 0; _i < 4; _i++) {                                          \
        int _idx = tid + _i * 256;                                            \
        int _row = _idx >> 3, _cj = _idx & 7;                                 \
        uint32_t _da = aBase + (buf) * 36864u + _row * 144u + _cj * 16u;      \
        const float* _ga = A + (size_t)(bm + _row) * lda + _k0 + _cj * 4;     \
        asm volatile("cp.async.cg.shared.global [%0], [%1], 16;"              \
                     :: "r"(_da), "l"(_ga));                                  \
        uint32_t _db = aBase + (buf) * 36864u + 18432u + _row * 144u + _cj * 16u; \
        int _ok = (bn + _row < Brows);                                        \
        const float* _gb = _ok ? (B + (size_t)(bn + _row) * ldb + _k0 + _cj * 4) : B; \
        int _sz = _ok ? 16 : 0;                                               \
        asm volatile("cp.async.cg.shared.global [%0], [%1], 16, %2;"          \
                     :: "r"(_db), "l"(_gb), "r"(_sz));                        \
    }                                                                         \
    asm volatile("cp.async.commit_group;" ::: "memory");                      \
} while (0)

    LOAD_TILE(0, 0);
    if (niter > 1) LOAD_TILE(1, 1);

    for (int kt = 0; kt < niter; kt++) {
        if (kt + 1 < niter)
            asm volatile("cp.async.wait_group 1;" ::: "memory");
        else
            asm volatile("cp.async.wait_group 0;" ::: "memory");
        __syncthreads();

        if (kt + 2 < niter) {
            int nb = kt + 2 - ((kt + 2) / 3) * 3;
            LOAD_TILE(nb, kt + 2);
        }

        const int buf = kt - (kt / 3) * 3;
        const float* as = sm + buf * 9216;
        const float* bs = as + 4608;
#pragma unroll
        for (int ks = 0; ks < 4; ks++) {
            uint32_t a[4][4], b[4][2];
            const int r0 = wm * 64 + (lane >> 2);
            const int c0 = ks * 8 + (lane & 3);
#pragma unroll
            for (int mi = 0; mi < 4; mi++) {
                a[mi][0] = __float_as_uint(as[(r0 + mi * 16) * 36 + c0]);
                a[mi][1] = __float_as_uint(as[(r0 + mi * 16 + 8) * 36 + c0]);
                a[mi][2] = __float_as_uint(as[(r0 + mi * 16) * 36 + c0 + 4]);
                a[mi][3] = __float_as_uint(as[(r0 + mi * 16 + 8) * 36 + c0 + 4]);
            }
            const int n0 = wn * 32 + (lane >> 2);
#pragma unroll
            for (int ni = 0; ni < 4; ni++) {
                b[ni][0] = __float_as_uint(bs[(n0 + ni * 8) * 36 + c0]);
                b[ni][1] = __float_as_uint(bs[(n0 + ni * 8) * 36 + c0 + 4]);
            }
#pragma unroll
            for (int mi = 0; mi < 4; mi++)
#pragma unroll
                for (int ni = 0; ni < 4; ni++)
                    mma_tf32(acc[mi][ni], a[mi], b[ni]);
        }
    }
#undef LOAD_TILE

#pragma unroll
    for (int mi = 0; mi < 4; mi++)
#pragma unroll
        for (int ni = 0; ni < 4; ni++)
#pragma unroll
            for (int e = 0; e < 4; e++) {
                int m = bm + wm * 64 + mi * 16 + (lane >> 2) + ((e >= 2) ? 8 : 0);
                int n = bn + wn * 32 + ni * 8 + 2 * (lane & 3) + (e & 1);
                float v = 0.0f;
                if (n < Nreal) {
                    v = acc[mi][ni][e];
                    if (bias)  v += bias[n];
                    if (bias2) v += bias2[n];
                    if (relu)  v = fmaxf(v, 0.0f);
                }
                if (sec == 0) {
                    if (n < Nreal) out[(size_t)m * ldOut + n] = v;
                } else if (n < NpadStore) {
                    float hi = tf32r(v);
                    float* p = out + (size_t)m * ldOut;
                    p[n] = hi; p[sec + n] = v - hi; p[2 * sec + n] = hi;
                }
            }
}

// ---------- prep kernels ----------
__global__ void build_A1(const float* __restrict__ s0, const float* __restrict__ s1,
                         const float* __restrict__ s2, const int* __restrict__ epPtr,
                         float* __restrict__ A1)
{
    int k = blockIdx.x * 256 + threadIdx.x;
    int m = blockIdx.y;
    if (k >= 9248) return;
    float v = 0.0f;
    if (k < 4608)       v = s0[(size_t)m * 4608 + k];
    else if (k < 9216)  v = s1[(size_t)m * 4608 + (k - 4608)];
    else if (k < 9224)  v = s2[m * 8 + (k - 9216)];
    else if (k == 9224) v = epPtr ? (float)(*epPtr) : 0.0f;
    float hi = tf32r(v);
    size_t b = (size_t)m * 27744;
    A1[b + k] = hi; A1[b + 9248 + k] = v - hi; A1[b + 18496 + k] = hi;
}

__global__ void tsplit(const float* __restrict__ W, int K, int N,
                       float* __restrict__ out, int Kpad)
{
    __shared__ float t[32][33];
    int kb = blockIdx.x * 32, nb = blockIdx.y * 32;
    int tx = threadIdx.x, ty = threadIdx.y;
#pragma unroll
    for (int r = 0; r < 4; r++) {
        int k = kb + ty + r * 8, n = nb + tx;
        t[ty + r * 8][tx] = (k < K && n < N) ? W[(size_t)k * N + n] : 0.0f;
    }
    __syncthreads();
#pragma unroll
    for (int r = 0; r < 4; r++) {
        int n = nb + ty + r * 8, k = kb + tx;
        float v = t[tx][ty + r * 8];
        float hi = tf32r(v);
        size_t b = (size_t)n * (3 * (size_t)Kpad);
        out[b + k] = hi; out[b + Kpad + k] = hi; out[b + 2 * Kpad + k] = v - hi;
    }
}

__global__ void split_lstm(const float* __restrict__ Wih, const float* __restrict__ Whh,
                           float* __restrict__ out)
{
    int idx = blockIdx.x * 256 + threadIdx.x;
    if (idx >= 2048 * 512) return;
    int n = idx >> 9, k = idx & 511;
    float a = Wih[idx], c = Whh[idx];
    float ah = tf32r(a), ch = tf32r(c);
    size_t b = (size_t)n * 3072;
    out[b + k] = ah;            out[b + 512 + k] = ch;
    out[b + 1024 + k] = ah;     out[b + 1536 + k] = ch;
    out[b + 2048 + k] = a - ah; out[b + 2560 + k] = c - ch;
}

__global__ void h0split(const float* __restrict__ h0, float* __restrict__ AL)
{
    int idx = blockIdx.x * 256 + threadIdx.x;
    if (idx >= NB * 512) return;
    int m = idx >> 9, c = idx & 511;
    float v = h0[idx];
    float hi = tf32r(v);
    size_t b = (size_t)m * 3072;
    AL[b + 512 + c] = hi; AL[b + 1536 + c] = v - hi; AL[b + 2560 + c] = hi;
}

__global__ void lstm_kernel(const float* __restrict__ gates,
                            const float* __restrict__ c0, float* __restrict__ za)
{
    int i = blockIdx.x * blockDim.x + threadIdx.x;
    if (i >= NB * 512) return;
    int m = i >> 9, c = i & 511;
    const float* gr = gates + (size_t)m * 2048;
    float gi = gr[c], gf = gr[512 + c], gg = gr[1024 + c], go = gr[1536 + c];
    float si = 1.0f / (1.0f + expf(-gi));
    float sf = 1.0f / (1.0f + expf(-gf));
    float so = 1.0f / (1.0f + expf(-go));
    float cc = sf * c0[i] + si * tanhf(gg);
    float z = so * tanhf(cc);
    float hi = tf32r(z);
    size_t b = (size_t)m * 1632;
    za[b + c] = hi; za[b + 544 + c] = z - hi; za[b + 1088 + c] = hi;
}

__global__ void sample_kernel(const float* __restrict__ logits,
                              float* __restrict__ zin,
                              float* __restrict__ outAction,
                              float* __restrict__ lpAcc,
                              float* __restrict__ entAcc,
                              uint32_t sk0, uint32_t sk1, int head)
{
    int warp = (blockIdx.x * blockDim.x + threadIdx.x) >> 5;
    int lane = threadIdx.x & 31;
    if (warp >= NB) return;
    int r = warp;

    float x0 = logits[r * 64 + lane];
    float x1 = logits[r * 64 + 32 + lane];

    float mx = fmaxf(x0, x1);
#pragma unroll
    for (int o = 16; o; o >>= 1) mx = fmaxf(mx, __shfl_xor_sync(0xffffffffu, mx, o));
    float s = expf(x0 - mx) + expf(x1 - mx);
#pragma unroll
    for (int o = 16; o; o >>= 1) s += __shfl_xor_sync(0xffffffffu, s, o);
    float lse = mx + logf(s);

    float t = expf(x0 - lse) * (lse - x0) + expf(x1 - lse) * (lse - x1);
#pragma unroll
    for (int o = 16; o; o >>= 1) t += __shfl_xor_sync(0xffffffffu, t, o);

    float g0 = gumbel_for(sk0, sk1, (uint32_t)(r * 64 + lane));
    float g1 = gumbel_for(sk0, sk1, (uint32_t)(r * 64 + 32 + lane));
    float ya = x0 + g0, yb = x1 + g1;
    float y; int idx;
    if (ya >= yb) { y = ya; idx = lane; } else { y = yb; idx = lane + 32; }
#pragma unroll
    for (int o = 16; o; o >>= 1) {
        float oy = __shfl_xor_sync(0xffffffffu, y, o);
        int   oi = __shfl_xor_sync(0xffffffffu, idx, o);
        if (oy > y || (oy == y && oi < idx)) { y = oy; idx = oi; }
    }
    int src = idx & 31;
    float v0 = __shfl_sync(0xffffffffu, x0, src);
    float v1 = __shfl_sync(0xffffffffu, x1, src);
    float xw = (idx < 32) ? v0 : v1;

    if (lane == 0) {
        float a = (float)idx;
        size_t b = (size_t)r * 1632;
        zin[b + 512] = a;
        zin[b + 544 + 512] = 0.0f;
        zin[b + 1088 + 512] = a;
        outAction[r * 8 + head] = a;
        lpAcc[r] += xw - lse;
        entAcc[r] += t;
    }
}

__global__ void init_kernel(float* __restrict__ lp, float* __restrict__ ent)
{
    int i = blockIdx.x * blockDim.x + threadIdx.x;
    if (i < NB) { lp[i] = 0.0f; ent[i] = 0.0f; }
}

__global__ void reduce_ent(const float* __restrict__ ent, float* __restrict__ out)
{
    __shared__ float sm[256];
    float s = 0.0f;
    for (int i = threadIdx.x; i < NB; i += 256) s += ent[i];
    sm[threadIdx.x] = s;
    __syncthreads();
    for (int o = 128; o; o >>= 1) {
        if (threadIdx.x < o) sm[threadIdx.x] += sm[threadIdx.x + o];
        __syncthreads();
    }
    if (threadIdx.x == 0) out[0] = sm[0];
}

// ---------- host launcher ----------
extern "C" void kernel_launch(void* const* d_in, const int* in_sizes, int n_in,
                              void* d_out, int out_size)
{
    const float* actual    = (const float*)d_in[0];
    const float* objective = (const float*)d_in[1];
    const float* last      = (const float*)d_in[2];

    int base = 4;
    const int* epPtr = nullptr;
    if (in_sizes[3] == 1) epPtr = (const int*)d_in[3];
    else base = 3;

    const float* W1  = (const float*)d_in[base + 0];
    const float* b1  = (const float*)d_in[base + 1];
    const float* W2  = (const float*)d_in[base + 2];
    const float* b2  = (const float*)d_in[base + 3];
    const float* W3  = (const float*)d_in[base + 4];
    const float* b3  = (const float*)d_in[base + 5];
    const float* Wih = (const float*)d_in[base + 6];
    const float* Whh = (const float*)d_in[base + 7];
    const float* bih = (const float*)d_in[base + 8];
    const float* bhh = (const float*)d_in[base + 9];
    const float* h0  = (const float*)d_in[base + 10];
    const float* c0  = (const float*)d_in[base + 11];
    const float* dW1 = (const float*)d_in[base + 12];
    const float* db1 = (const float*)d_in[base + 13];

    const float* headW[8];
    const float* headb[8];
    const float* dWo;
    const float* dbo;
    if (n_in >= base + 32) {
        for (int i = 0; i < 8; i++) {
            headW[i] = (const float*)d_in[base + 14 + i];
            headb[i] = (const float*)d_in[base + 22 + i];
        }
        dWo = (const float*)d_in[base + 30];
        dbo = (const float*)d_in[base + 31];
    } else {
        const float* hw = (const float*)d_in[base + 14];
        const float* hb = (const float*)d_in[base + 15];
        for (int i = 0; i < 8; i++) {
            headW[i] = hw + (size_t)i * 256 * 64;
            headb[i] = hb + (size_t)i * 64;
        }
        dWo = (const float*)d_in[base + 16];
        dbo = (const float*)d_in[base + 17];
    }
    const int D1 = in_sizes[base + 1];  // 3518
    const int D2 = in_sizes[base + 3];  // 1342

    float* sc = nullptr;
    cudaGetSymbolAddress((void**)&sc, g_scratch);
    float* A1 = sc + OFF_A1;   float* A2 = sc + OFF_A2;
    float* B1 = sc + OFF_B1;   float* B2 = sc + OFF_B2;
    float* A3 = sc + OFF_A3;   float* B3 = sc + OFF_B3;
    float* AL = sc + OFF_AL;   float* BL = sc + OFF_BL;
    float* gates = sc + OFF_G;
    float* za = sc + OFF_ZA;   float* zb = sc + OFF_ZB;
    float* Z1 = sc + OFF_Z1;
    float* BD1 = sc + OFF_BD1; float* BDO = sc + OFF_BDO;
    float* BH = sc + OFF_BH;
    float* logb = sc + OFF_LOG;
    float* entb = sc + OFF_ENT;

    float* out  = (float*)d_out;
    float* lp   = out + NB * 8 + 1;
    float* entO = out + NB * 8;

    uint32_t k0 = 0u, k1 = 42u, sk0[8], sk1[8];
    for (int t = 0; t < 8; t++) {
        uint32_t n0, n1, s0, s1;
        threefry2x32(k0, k1, 0u, 0u, &n0, &n1);
        threefry2x32(k0, k1, 0u, 1u, &s0, &s1);
        sk0[t] = s0; sk1[t] = s1;
        k0 = n0; k1 = n1;
    }

    const int SMEM = 3 * 36864;  // 110592 B
    cudaFuncSetAttribute(mma_gemm, cudaFuncAttributeMaxDynamicSharedMemorySize, SMEM);

    dim3 blk(256);
    dim3 tsb(32, 8);

    init_kernel<<<(NB + 255) / 256, blk>>>(lp, entb);

    // weight prep
    tsplit<<<dim3(289, 112), tsb>>>(W1, 9225, D1, B1, 9248);
    tsplit<<<dim3(110, 48),  tsb>>>(W2, D1, D2, B2, 3520);
    tsplit<<<dim3(42, 16),   tsb>>>(W3, D2, 512, B3, 1344);
    split_lstm<<<(2048 * 512 + 255) / 256, blk>>>(Wih, Whh, BL);
    h0split<<<(NB * 512 + 255) / 256, blk>>>(h0, AL);
    tsplit<<<dim3(17, 8),  tsb>>>(dW1, 512, 256, BD1, 544);
    tsplit<<<dim3(17, 16), tsb>>>(dWo, 513, 512, BDO, 544);
    for (int t = 0; t < 8; t++)
        tsplit<<<dim3(8, 2), tsb>>>(headW[t], 256, 64, BH + (size_t)t * 49152, 256);
    build_A1<<<dim3(37, 4096), blk>>>(actual, objective, last, epPtr, A1);

    // encoder
    mma_gemm<<<dim3(28, 32), blk, SMEM>>>(A1, 27744, B1, 27744, 3520, 27744,
        b1, nullptr, A2, 10560, 3520, D1, 3520, 1);
    mma_gemm<<<dim3(11, 32), blk, SMEM>>>(A2, 10560, B2, 10560, 1344, 10560,
        b2, nullptr, A3, 4032, 1344, D2, 1344, 1);
    mma_gemm<<<dim3(4, 32), blk, SMEM>>>(A3, 4032, B3, 4032, 512, 4032,
        b3, nullptr, AL, 3072, 1024, 512, 512, 1);

    // LSTM
    mma_gemm<<<dim3(16, 32), blk, SMEM>>>(AL, 3072, BL, 3072, 2048, 3072,
        bih, bhh, gates, 2048, 0, 2048, 0, 0);
    lstm_kernel<<<(NB * 512 + 255) / 256, blk>>>(gates, c0, za);

    // decoder
    for (int t = 0; t < 8; t++) {
        float* zin  = (t & 1) ? zb : za;
        float* zout = (t & 1) ? za : zb;
        mma_gemm<<<dim3(2, 32), blk, SMEM>>>(zin, 1632, BD1, 1632, 256, 1632,
            db1, nullptr, Z1, 768, 256, 256, 256, 1);
        mma_gemm<<<dim3(1, 32), blk, SMEM>>>(Z1, 768, BH + (size_t)t * 49152, 768, 64, 768,
            headb[t], nullptr, logb, 64, 0, 64, 0, 0);
        sample_kernel<<<NB / 8, blk>>>(logb, zin, out, lp, entb, sk0[t], sk1[t], t);
        mma_gemm<<<dim3(4, 32), blk, SMEM>>>(zin, 1632, BDO, 1632, 512, 1632,
            dbo, nullptr, zout, 1632, 544, 512, 512, 1);
    }

    reduce_ent<<<1, blk>>>(entb, entO);
}

// round 7
// speedup vs baseline: 1.1331x; 1.0058x over previous
#include <cuda_runtime.h>
#include <stdint.h>
#include <math.h>

#define NB 4096

__device__ float g_scratch[224894976];

#define A1HI 0u
#define A1LO 37879808u
#define B1HI 75759616u
#define B1LO 108312576u
#define A2HI 140865536u
#define A2LO 155283456u
#define B2HI 169701376u
#define B2LO 174432256u
#define A3HI 179163136u
#define A3LO 184668160u
#define B3HI 190173184u
#define B3LO 190861312u
#define ALHI 191549440u
#define ALLO 195743744u
#define BLHI 199938048u
#define BLLO 202035200u
#define GOFF 204132352u
#define ZAHI 212520960u
#define ZALO 214749184u
#define ZBHI 216977408u
#define ZBLO 219205632u
#define Z1HI 221433856u
#define Z1LO 222482432u
#define BD1HI 223531008u
#define BD1LO 223670272u
#define BDOHI 223809536u
#define BDOLO 224088064u
#define BHHI 224366592u
#define BHLO 224497664u
#define LOGO 224628736u
#define ENTO 224890880u

__device__ __forceinline__ uint32_t smem_u32(const void* p) {
    uint32_t a;
    asm("{ .reg .u64 t; cvta.to.shared.u64 t, %1; cvt.u32.u64 %0, t; }" : "=r"(a) : "l"(p));
    return a;
}
__device__ __forceinline__ float tf32r(float x) {
    uint32_t u; asm("cvt.rna.tf32.f32 %0, %1;" : "=r"(u) : "f"(x)); return __uint_as_float(u);
}

// ---------- threefry (JAX partitionable) ----------
__host__ __device__ __forceinline__ void threefry2x32(
    uint32_t k0, uint32_t k1, uint32_t x0, uint32_t x1, uint32_t* o0, uint32_t* o1)
{
    uint32_t ks0 = k0, ks1 = k1, ks2 = 0x1BD11BDAu ^ k0 ^ k1;
    x0 += ks0; x1 += ks1;
#define TF_ROUND(r) do { x0 += x1; x1 = (x1 << (r)) | (x1 >> (32 - (r))); x1 ^= x0; } while (0)
    TF_ROUND(13); TF_ROUND(15); TF_ROUND(26); TF_ROUND(6);
    x0 += ks1; x1 += ks2 + 1u;
    TF_ROUND(17); TF_ROUND(29); TF_ROUND(16); TF_ROUND(24);
    x0 += ks2; x1 += ks0 + 2u;
    TF_ROUND(13); TF_ROUND(15); TF_ROUND(26); TF_ROUND(6);
    x0 += ks0; x1 += ks1 + 3u;
    TF_ROUND(17); TF_ROUND(29); TF_ROUND(16); TF_ROUND(24);
    x0 += ks1; x1 += ks2 + 4u;
    TF_ROUND(13); TF_ROUND(15); TF_ROUND(26); TF_ROUND(6);
    x0 += ks2; x1 += ks0 + 5u;
#undef TF_ROUND
    *o0 = x0; *o1 = x1;
}
__device__ __forceinline__ float gumbel_for(uint32_t k0, uint32_t k1, uint32_t j)
{
    uint32_t o0, o1;
    threefry2x32(k0, k1, 0u, j, &o0, &o1);
    uint32_t bits = o0 ^ o1;
    uint32_t fb = (bits >> 9) | 0x3f800000u;
    float f = __uint_as_float(fb) - 1.0f;
    if (f == 0.0f) f = 1.1754943508222875e-38f;
    return -logf(-logf(f));
}

__device__ __forceinline__ void mma_tf32(float* c, const uint32_t* a, const uint32_t* b)
{
    asm volatile(
        "mma.sync.aligned.m16n8k8.row.col.f32.tf32.tf32.f32 "
        "{%0,%1,%2,%3}, {%4,%5,%6,%7}, {%8,%9}, {%0,%1,%2,%3};"
        : "+f"(c[0]), "+f"(c[1]), "+f"(c[2]), "+f"(c[3])
        : "r"(a[0]), "r"(a[1]), "r"(a[2]), "r"(a[3]), "r"(b[0]), "r"(b[1]));
}

// ==================================================================
// tf32 mma.sync GEMM, 3xTF32 sections via pointer select.
// 128x128 tile, 256 threads, 2-stage cp.async, 2 CTAs/SM (R4 core).
// A sections: [hi | lo | hi], B sections: [hi | hi | lo]; pitch = Kpad.
// outLo != null: relu + split store (hi/lo); else plain store.
// ==================================================================
__global__ void __launch_bounds__(256, 2)
mma_gemm(const float* __restrict__ Ahi, const float* __restrict__ Alo, int lda,
         const float* __restrict__ Bhi, const float* __restrict__ Blo, int ldb,
         int Brows, int Kpad,
         const float* __restrict__ bias, const float* __restrict__ bias2,
         float* __restrict__ outHi, float* __restrict__ outLo, int ldOut,
         int Nreal)
{
    extern __shared__ float sm[];
    const int tid  = threadIdx.x;
    const int bm   = blockIdx.y * 128;
    const int bn   = blockIdx.x * 128;
    const int lane = tid & 31;
    const int wid  = tid >> 5;
    const int wm   = wid >> 2;
    const int wn   = wid & 3;
    const int nSec = Kpad >> 5;
    const int niter = 3 * nSec;

    const uint32_t aBase = smem_u32(sm);
    const uint32_t bBase = aBase + 2u * 18432u;

    float acc[4][4][4];
#pragma unroll
    for (int i = 0; i < 4; i++)
#pragma unroll
        for (int j = 0; j < 4; j++)
#pragma unroll
            for (int e = 0; e < 4; e++) acc[i][j][e] = 0.0f;

#define LOAD_TILE(buf, kt) do {                                               \
    int _s = (((kt) >= nSec) ? 1 : 0) + (((kt) >= 2 * nSec) ? 1 : 0);         \
    int _k0 = ((kt) - _s * nSec) * 32;                                        \
    const float* _A = (_s == 1) ? Alo : Ahi;                                  \
    const float* _B = (_s == 2) ? Blo : Bhi;                                  \
    _Pragma("unroll")                                                         \
    for (int _i = 0; _i < 4; _i++) {                                          \
        int _idx = tid + _i * 256;                                            \
        int _row = _idx >> 3, _cj = _idx & 7;                                 \
        uint32_t _da = aBase + (buf) * 18432u + _row * 144u + _cj * 16u;      \
        const float* _ga = _A + (size_t)(bm + _row) * lda + _k0 + _cj * 4;    \
        asm volatile("cp.async.cg.shared.global [%0], [%1], 16;"              \
                     :: "r"(_da), "l"(_ga));                                  \
        uint32_t _db = bBase + (buf) * 18432u + _row * 144u + _cj * 16u;      \
        int _ok = (bn + _row < Brows);                                        \
        const float* _gb = _ok ? (_B + (size_t)(bn + _row) * ldb + _k0 + _cj * 4) : _B; \
        int _sz = _ok ? 16 : 0;                                               \
        asm volatile("cp.async.cg.shared.global [%0], [%1], 16, %2;"          \
                     :: "r"(_db), "l"(_gb), "r"(_sz));                        \
    }                                                                         \
    asm volatile("cp.async.commit_group;" ::: "memory");                      \
} while (0)

    LOAD_TILE(0, 0);

    for (int kt = 0; kt < niter; kt++) {
        const int buf = kt & 1;
        if (kt + 1 < niter) {
            LOAD_TILE(buf ^ 1, kt + 1);
            asm volatile("cp.async.wait_group 1;" ::: "memory");
        } else {
            asm volatile("cp.async.wait_group 0;" ::: "memory");
        }
        __syncthreads();

        const float* as = sm + buf * 4608;
        const float* bs = sm + 2 * 4608 + buf * 4608;
#pragma unroll
        for (int ks = 0; ks < 4; ks++) {
            uint32_t a[4][4], b[4][2];
            const int r0 = wm * 64 + (lane >> 2);
            const int c0 = ks * 8 + (lane & 3);
#pragma unroll
            for (int mi = 0; mi < 4; mi++) {
                a[mi][0] = __float_as_uint(as[(r0 + mi * 16) * 36 + c0]);
                a[mi][1] = __float_as_uint(as[(r0 + mi * 16 + 8) * 36 + c0]);
                a[mi][2] = __float_as_uint(as[(r0 + mi * 16) * 36 + c0 + 4]);
                a[mi][3] = __float_as_uint(as[(r0 + mi * 16 + 8) * 36 + c0 + 4]);
            }
            const int n0 = wn * 32 + (lane >> 2);
#pragma unroll
            for (int ni = 0; ni < 4; ni++) {
                b[ni][0] = __float_as_uint(bs[(n0 + ni * 8) * 36 + c0]);
                b[ni][1] = __float_as_uint(bs[(n0 + ni * 8) * 36 + c0 + 4]);
            }
#pragma unroll
            for (int mi = 0; mi < 4; mi++)
#pragma unroll
                for (int ni = 0; ni < 4; ni++)
                    mma_tf32(acc[mi][ni], a[mi], b[ni]);
        }
        __syncthreads();
    }
#undef LOAD_TILE

#pragma unroll
    for (int mi = 0; mi < 4; mi++)
#pragma unroll
        for (int ni = 0; ni < 4; ni++)
#pragma unroll
            for (int e = 0; e < 4; e++) {
                int m = bm + wm * 64 + mi * 16 + (lane >> 2) + ((e >= 2) ? 8 : 0);
                int n = bn + wn * 32 + ni * 8 + 2 * (lane & 3) + (e & 1);
                if (n >= Nreal) continue;
                float v = acc[mi][ni][e];
                if (bias)  v += bias[n];
                if (bias2) v += bias2[n];
                if (outLo) {
                    v = fmaxf(v, 0.0f);
                    float hi = tf32r(v);
                    outHi[(size_t)m * ldOut + n] = hi;
                    outLo[(size_t)m * ldOut + n] = v - hi;
                } else {
                    outHi[(size_t)m * ldOut + n] = v;
                }
            }
}

// ---------- prep kernels ----------
__global__ void build_A1(const float* __restrict__ s0, const float* __restrict__ s1,
                         const float* __restrict__ s2, const int* __restrict__ epPtr,
                         float* __restrict__ Ahi, float* __restrict__ Alo)
{
    int k = blockIdx.x * 256 + threadIdx.x;
    int m = blockIdx.y;
    if (k >= 9248) return;
    float v = 0.0f;
    if (k < 4608)       v = s0[(size_t)m * 4608 + k];
    else if (k < 9216)  v = s1[(size_t)m * 4608 + (k - 4608)];
    else if (k < 9224)  v = s2[m * 8 + (k - 9216)];
    else if (k == 9224) v = epPtr ? (float)(*epPtr) : 0.0f;
    float hi = tf32r(v);
    size_t b = (size_t)m * 9248 + k;
    Ahi[b] = hi; Alo[b] = v - hi;
}

// W[K,N] row-major -> outHi/outLo[n][Kpad] (transposed, zero-padded)
__global__ void tsplit(const float* __restrict__ W, int K, int N,
                       float* __restrict__ outHi, float* __restrict__ outLo, int Kpad)
{
    __shared__ float t[32][33];
    int kb = blockIdx.x * 32, nb = blockIdx.y * 32;
    int tx = threadIdx.x, ty = threadIdx.y;
#pragma unroll
    for (int r = 0; r < 4; r++) {
        int k = kb + ty + r * 8, n = nb + tx;
        t[ty + r * 8][tx] = (k < K && n < N) ? W[(size_t)k * N + n] : 0.0f;
    }
    __syncthreads();
#pragma unroll
    for (int r = 0; r < 4; r++) {
        int n = nb + ty + r * 8, k = kb + tx;
        float v = t[tx][ty + r * 8];
        float hi = tf32r(v);
        size_t b = (size_t)n * Kpad + k;
        outHi[b] = hi; outLo[b] = v - hi;
    }
}

__global__ void split_lstm(const float* __restrict__ Wih, const float* __restrict__ Whh,
                           float* __restrict__ outHi, float* __restrict__ outLo)
{
    int idx = blockIdx.x * 256 + threadIdx.x;
    if (idx >= 2048 * 512) return;
    int n = idx >> 9, k = idx & 511;
    float a = Wih[idx], c = Whh[idx];
    float ah = tf32r(a), ch = tf32r(c);
    size_t b = (size_t)n * 1024;
    outHi[b + k] = ah;       outHi[b + 512 + k] = ch;
    outLo[b + k] = a - ah;   outLo[b + 512 + k] = c - ch;
}

__global__ void h0split(const float* __restrict__ h0,
                        float* __restrict__ ALhi, float* __restrict__ ALlo)
{
    int idx = blockIdx.x * 256 + threadIdx.x;
    if (idx >= NB * 512) return;
    int m = idx >> 9, c = idx & 511;
    float v = h0[idx];
    float hi = tf32r(v);
    size_t b = (size_t)m * 1024 + 512 + c;
    ALhi[b] = hi; ALlo[b] = v - hi;
}

__global__ void lstm_kernel(const float* __restrict__ gates,
                            const float* __restrict__ c0,
                            float* __restrict__ zhi, float* __restrict__ zlo)
{
    int i = blockIdx.x * blockDim.x + threadIdx.x;
    if (i >= NB * 512) return;
    int m = i >> 9, c = i & 511;
    const float* gr = gates + (size_t)m * 2048;
    float gi = gr[c], gf = gr[512 + c], gg = gr[1024 + c], go = gr[1536 + c];
    float si = 1.0f / (1.0f + expf(-gi));
    float sf = 1.0f / (1.0f + expf(-gf));
    float so = 1.0f / (1.0f + expf(-go));
    float cc = sf * c0[i] + si * tanhf(gg);
    float z = so * tanhf(cc);
    float hi = tf32r(z);
    size_t b = (size_t)m * 544 + c;
    zhi[b] = hi; zlo[b] = z - hi;
}

__global__ void sample_kernel(const float* __restrict__ logits,
                              float* __restrict__ zinHi, float* __restrict__ zinLo,
                              float* __restrict__ outAction,
                              float* __restrict__ lpAcc,
                              float* __restrict__ entAcc,
                              uint32_t sk0, uint32_t sk1, int head)
{
    int warp = (blockIdx.x * blockDim.x + threadIdx.x) >> 5;
    int lane = threadIdx.x & 31;
    if (warp >= NB) return;
    int r = warp;

    float x0 = logits[r * 64 + lane];
    float x1 = logits[r * 64 + 32 + lane];

    float mx = fmaxf(x0, x1);
#pragma unroll
    for (int o = 16; o; o >>= 1) mx = fmaxf(mx, __shfl_xor_sync(0xffffffffu, mx, o));
    float s = expf(x0 - mx) + expf(x1 - mx);
#pragma unroll
    for (int o = 16; o; o >>= 1) s += __shfl_xor_sync(0xffffffffu, s, o);
    float lse = mx + logf(s);

    float t = expf(x0 - lse) * (lse - x0) + expf(x1 - lse) * (lse - x1);
#pragma unroll
    for (int o = 16; o; o >>= 1) t += __shfl_xor_sync(0xffffffffu, t, o);

    float g0 = gumbel_for(sk0, sk1, (uint32_t)(r * 64 + lane));
    float g1 = gumbel_for(sk0, sk1, (uint32_t)(r * 64 + 32 + lane));
    float ya = x0 + g0, yb = x1 + g1;
    float y; int idx;
    if (ya >= yb) { y = ya; idx = lane; } else { y = yb; idx = lane + 32; }
#pragma unroll
    for (int o = 16; o; o >>= 1) {
        float oy = __shfl_xor_sync(0xffffffffu, y, o);
        int   oi = __shfl_xor_sync(0xffffffffu, idx, o);
        if (oy > y || (oy == y && oi < idx)) { y = oy; idx = oi; }
    }
    int src = idx & 31;
    float v0 = __shfl_sync(0xffffffffu, x0, src);
    float v1 = __shfl_sync(0xffffffffu, x1, src);
    float xw = (idx < 32) ? v0 : v1;

    if (lane == 0) {
        float a = (float)idx;
        size_t b = (size_t)r * 544 + 512;
        zinHi[b] = a;
        zinLo[b] = 0.0f;   // act exact in tf32
        outAction[r * 8 + head] = a;
        lpAcc[r] += xw - lse;
        entAcc[r] += t;
    }
}

__global__ void init_kernel(float* __restrict__ lp, float* __restrict__ ent)
{
    int i = blockIdx.x * blockDim.x + threadIdx.x;
    if (i < NB) { lp[i] = 0.0f; ent[i] = 0.0f; }
}

__global__ void reduce_ent(const float* __restrict__ ent, float* __restrict__ out)
{
    __shared__ float sm[256];
    float s = 0.0f;
    for (int i = threadIdx.x; i < NB; i += 256) s += ent[i];
    sm[threadIdx.x] = s;
    __syncthreads();
    for (int o = 128; o; o >>= 1) {
        if (threadIdx.x < o) sm[threadIdx.x] += sm[threadIdx.x + o];
        __syncthreads();
    }
    if (threadIdx.x == 0) out[0] = sm[0];
}

// ---------- host launcher ----------
extern "C" void kernel_launch(void* const* d_in, const int* in_sizes, int n_in,
                              void* d_out, int out_size)
{
    const float* actual    = (const float*)d_in[0];
    const float* objective = (const float*)d_in[1];
    const float* last      = (const float*)d_in[2];

    int base = 4;
    const int* epPtr = nullptr;
    if (in_sizes[3] == 1) epPtr = (const int*)d_in[3];
    else base = 3;

    const float* W1  = (const float*)d_in[base + 0];
    const float* b1  = (const float*)d_in[base + 1];
    const float* W2  = (const float*)d_in[base + 2];
    const float* b2  = (const float*)d_in[base + 3];
    const float* W3  = (const float*)d_in[base + 4];
    const float* b3  = (const float*)d_in[base + 5];
    const float* Wih = (const float*)d_in[base + 6];
    const float* Whh = (const float*)d_in[base + 7];
    const float* bih = (const float*)d_in[base + 8];
    const float* bhh = (const float*)d_in[base + 9];
    const float* h0  = (const float*)d_in[base + 10];
    const float* c0  = (const float*)d_in[base + 11];
    const float* dW1 = (const float*)d_in[base + 12];
    const float* db1 = (const float*)d_in[base + 13];

    const float* headW[8];
    const float* headb[8];
    const float* dWo;
    const float* dbo;
    if (n_in >= base + 32) {
        for (int i = 0; i < 8; i++) {
            headW[i] = (const float*)d_in[base + 14 + i];
            headb[i] = (const float*)d_in[base + 22 + i];
        }
        dWo = (const float*)d_in[base + 30];
        dbo = (const float*)d_in[base + 31];
    } else {
        const float* hw = (const float*)d_in[base + 14];
        const float* hb = (const float*)d_in[base + 15];
        for (int i = 0; i < 8; i++) {
            headW[i] = hw + (size_t)i * 256 * 64;
            headb[i] = hb + (size_t)i * 64;
        }
        dWo = (const float*)d_in[base + 16];
        dbo = (const float*)d_in[base + 17];
    }
    const int D1 = in_sizes[base + 1];  // 3518
    const int D2 = in_sizes[base + 3];  // 1342

    float* sc = nullptr;
    cudaGetSymbolAddress((void**)&sc, g_scratch);
    float* a1hi = sc + A1HI;  float* a1lo = sc + A1LO;
    float* b1hi = sc + B1HI;  float* b1lo = sc + B1LO;
    float* a2hi = sc + A2HI;  float* a2lo = sc + A2LO;
    float* b2hi = sc + B2HI;  float* b2lo = sc + B2LO;
    float* a3hi = sc + A3HI;  float* a3lo = sc + A3LO;
    float* b3hi = sc + B3HI;  float* b3lo = sc + B3LO;
    float* alhi = sc + ALHI;  float* allo = sc + ALLO;
    float* blhi = sc + BLHI;  float* bllo = sc + BLLO;
    float* gates = sc + GOFF;
    float* zahi = sc + ZAHI;  float* zalo = sc + ZALO;
    float* zbhi = sc + ZBHI;  float* zblo = sc + ZBLO;
    float* z1hi = sc + Z1HI;  float* z1lo = sc + Z1LO;
    float* bd1hi = sc + BD1HI; float* bd1lo = sc + BD1LO;
    float* bdohi = sc + BDOHI; float* bdolo = sc + BDOLO;
    float* bhhi = sc + BHHI;  float* bhlo = sc + BHLO;
    float* logb = sc + LOGO;
    float* entb = sc + ENTO;

    float* out  = (float*)d_out;
    float* lp   = out + NB * 8 + 1;
    float* entO = out + NB * 8;

    uint32_t k0 = 0u, k1 = 42u, sk0[8], sk1[8];
    for (int t = 0; t < 8; t++) {
        uint32_t n0, n1, s0, s1;
        threefry2x32(k0, k1, 0u, 0u, &n0, &n1);
        threefry2x32(k0, k1, 0u, 1u, &s0, &s1);
        sk0[t] = s0; sk1[t] = s1;
        k0 = n0; k1 = n1;
    }

    const int SMEM = 4 * 18432;  // 73728 B (R4 config)
    cudaFuncSetAttribute(mma_gemm, cudaFuncAttributeMaxDynamicSharedMemorySize, SMEM);

    dim3 blk(256);
    dim3 tsb(32, 8);

    init_kernel<<<(NB + 255) / 256, blk>>>(lp, entb);

    // weight prep (hi/lo only)
    tsplit<<<dim3(289, 110), tsb>>>(W1, 9225, D1, b1hi, b1lo, 9248);
    tsplit<<<dim3(110, 42),  tsb>>>(W2, D1, D2, b2hi, b2lo, 3520);
    tsplit<<<dim3(42, 16),   tsb>>>(W3, D2, 512, b3hi, b3lo, 1344);
    split_lstm<<<(2048 * 512 + 255) / 256, blk>>>(Wih, Whh, blhi, bllo);
    h0split<<<(NB * 512 + 255) / 256, blk>>>(h0, alhi, allo);
    tsplit<<<dim3(17, 8),  tsb>>>(dW1, 512, 256, bd1hi, bd1lo, 544);
    tsplit<<<dim3(17, 16), tsb>>>(dWo, 513, 512, bdohi, bdolo, 544);
    for (int t = 0; t < 8; t++)
        tsplit<<<dim3(8, 2), tsb>>>(headW[t], 256, 64,
                                    bhhi + (size_t)t * 16384, bhlo + (size_t)t * 16384, 256);
    build_A1<<<dim3(37, 4096), blk>>>(actual, objective, last, epPtr, a1hi, a1lo);

    // encoder
    mma_gemm<<<dim3(28, 32), blk, SMEM>>>(a1hi, a1lo, 9248, b1hi, b1lo, 9248,
        3520, 9248, b1, nullptr, a2hi, a2lo, 3520, D1);
    mma_gemm<<<dim3(11, 32), blk, SMEM>>>(a2hi, a2lo, 3520, b2hi, b2lo, 3520,
        1344, 3520, b2, nullptr, a3hi, a3lo, 1344, D2);
    mma_gemm<<<dim3(4, 32), blk, SMEM>>>(a3hi, a3lo, 1344, b3hi, b3lo, 1344,
        512, 1344, b3, nullptr, alhi, allo, 1024, 512);

    // LSTM (plain store into gates)
    mma_gemm<<<dim3(16, 32), blk, SMEM>>>(alhi, allo, 1024, blhi, bllo, 1024,
        2048, 1024, bih, bhh, gates, nullptr, 2048, 2048);
    lstm_kernel<<<(NB * 512 + 255) / 256, blk>>>(gates, c0, zahi, zalo);

    // decoder
    for (int t = 0; t < 8; t++) {
        float* zihi = (t & 1) ? zbhi : zahi;
        float* zilo = (t & 1) ? zblo : zalo;
        float* zohi = (t & 1) ? zahi : zbhi;
        float* zolo = (t & 1) ? zalo : zblo;
        mma_gemm<<<dim3(2, 32), blk, SMEM>>>(zihi, zilo, 544, bd1hi, bd1lo, 544,
            256, 544, db1, nullptr, z1hi, z1lo, 256, 256);
        mma_gemm<<<dim3(1, 32), blk, SMEM>>>(z1hi, z1lo, 256,
            bhhi + (size_t)t * 16384, bhlo + (size_t)t * 16384, 256,
            64, 256, headb[t], nullptr, logb, nullptr, 64, 64);
        sample_kernel<<<NB / 8, blk>>>(logb, zihi, zilo, out, lp, entb, sk0[t], sk1[t], t);
        mma_gemm<<<dim3(4, 32), blk, SMEM>>>(zihi, zilo, 544, bdohi, bdolo, 544,
            512, 544, dbo, nullptr, zohi, zolo, 544, 512);
    }

    reduce_ent<<<1, blk>>>(entb, entO);
}

// round 8
// speedup vs baseline: 1.1985x; 1.0578x over previous
#include <cuda_runtime.h>
#include <stdint.h>
#include <math.h>

#define NB 4096

__device__ float g_scratch[224894976];

#define A1HI 0u
#define A1LO 37879808u
#define B1HI 75759616u
#define B1LO 108312576u
#define A2HI 140865536u
#define A2LO 155283456u
#define B2HI 169701376u
#define B2LO 174432256u
#define A3HI 179163136u
#define A3LO 184668160u
#define B3HI 190173184u
#define B3LO 190861312u
#define ALHI 191549440u
#define ALLO 195743744u
#define BLHI 199938048u
#define BLLO 202035200u
#define GOFF 204132352u
#define ZAHI 212520960u
#define ZALO 214749184u
#define ZBHI 216977408u
#define ZBLO 219205632u
#define Z1HI 221433856u
#define Z1LO 222482432u
#define BD1HI 223531008u
#define BD1LO 223670272u
#define BDOHI 223809536u
#define BDOLO 224088064u
#define BHHI 224366592u
#define BHLO 224497664u
#define LOGO 224628736u
#define ENTO 224890880u

__device__ __forceinline__ uint32_t smem_u32(const void* p) {
    uint32_t a;
    asm("{ .reg .u64 t; cvta.to.shared.u64 t, %1; cvt.u32.u64 %0, t; }" : "=r"(a) : "l"(p));
    return a;
}
__device__ __forceinline__ float tf32r(float x) {
    uint32_t u; asm("cvt.rna.tf32.f32 %0, %1;" : "=r"(u) : "f"(x)); return __uint_as_float(u);
}

// ---------- threefry (JAX partitionable) ----------
__host__ __device__ __forceinline__ void threefry2x32(
    uint32_t k0, uint32_t k1, uint32_t x0, uint32_t x1, uint32_t* o0, uint32_t* o1)
{
    uint32_t ks0 = k0, ks1 = k1, ks2 = 0x1BD11BDAu ^ k0 ^ k1;
    x0 += ks0; x1 += ks1;
#define TF_ROUND(r) do { x0 += x1; x1 = (x1 << (r)) | (x1 >> (32 - (r))); x1 ^= x0; } while (0)
    TF_ROUND(13); TF_ROUND(15); TF_ROUND(26); TF_ROUND(6);
    x0 += ks1; x1 += ks2 + 1u;
    TF_ROUND(17); TF_ROUND(29); TF_ROUND(16); TF_ROUND(24);
    x0 += ks2; x1 += ks0 + 2u;
    TF_ROUND(13); TF_ROUND(15); TF_ROUND(26); TF_ROUND(6);
    x0 += ks0; x1 += ks1 + 3u;
    TF_ROUND(17); TF_ROUND(29); TF_ROUND(16); TF_ROUND(24);
    x0 += ks1; x1 += ks2 + 4u;
    TF_ROUND(13); TF_ROUND(15); TF_ROUND(26); TF_ROUND(6);
    x0 += ks2; x1 += ks0 + 5u;
#undef TF_ROUND
    *o0 = x0; *o1 = x1;
}
__device__ __forceinline__ float gumbel_for(uint32_t k0, uint32_t k1, uint32_t j)
{
    uint32_t o0, o1;
    threefry2x32(k0, k1, 0u, j, &o0, &o1);
    uint32_t bits = o0 ^ o1;
    uint32_t fb = (bits >> 9) | 0x3f800000u;
    float f = __uint_as_float(fb) - 1.0f;
    if (f == 0.0f) f = 1.1754943508222875e-38f;
    return -logf(-logf(f));
}

__device__ __forceinline__ void mma_tf32(float* c, const uint32_t* a, const uint32_t* b)
{
    asm volatile(
        "mma.sync.aligned.m16n8k8.row.col.f32.tf32.tf32.f32 "
        "{%0,%1,%2,%3}, {%4,%5,%6,%7}, {%8,%9}, {%0,%1,%2,%3};"
        : "+f"(c[0]), "+f"(c[1]), "+f"(c[2]), "+f"(c[3])
        : "r"(a[0]), "r"(a[1]), "r"(a[2]), "r"(a[3]), "r"(b[0]), "r"(b[1]));
}

// ==================================================================
// fused 3xTF32 GEMM: per 16-wide k-chunk, load Ahi/Alo/Bhi/Blo once
// and accumulate hi*hi + lo*hi + hi*lo. 128x128 tile, 256 thr,
// 2-stage cp.async, 2 CTAs/SM.
// stage = 4 tiles x 128 rows x 20 floats = 40960 B; 2 stages = 81920 B
// ==================================================================
__global__ void __launch_bounds__(256, 2)
mma_gemm(const float* __restrict__ Ahi, const float* __restrict__ Alo, int lda,
         const float* __restrict__ Bhi, const float* __restrict__ Blo, int ldb,
         int Brows, int Kpad,
         const float* __restrict__ bias, const float* __restrict__ bias2,
         float* __restrict__ outHi, float* __restrict__ outLo, int ldOut,
         int Nreal)
{
    extern __shared__ float sm[];
    const int tid  = threadIdx.x;
    const int bm   = blockIdx.y * 128;
    const int bn   = blockIdx.x * 128;
    const int lane = tid & 31;
    const int wid  = tid >> 5;
    const int wm   = wid >> 2;
    const int wn   = wid & 3;
    const int niter = Kpad >> 4;

    const uint32_t base = smem_u32(sm);

    float acc[4][4][4];
#pragma unroll
    for (int i = 0; i < 4; i++)
#pragma unroll
        for (int j = 0; j < 4; j++)
#pragma unroll
            for (int e = 0; e < 4; e++) acc[i][j][e] = 0.0f;

#define LOAD_TILE(buf, kt) do {                                               \
    int _k0 = (kt) * 16;                                                      \
    _Pragma("unroll")                                                         \
    for (int _i = 0; _i < 8; _i++) {                                          \
        int _idx = tid + _i * 256;                                            \
        int _tile = _idx >> 9;                                                \
        int _rem  = _idx & 511;                                               \
        int _row  = _rem >> 2, _cj = _rem & 3;                                \
        uint32_t _dst = base + (buf) * 40960u + _tile * 10240u + _row * 80u + _cj * 16u; \
        const float* _src;                                                    \
        int _sz = 16;                                                         \
        if (_tile == 0)      _src = Ahi + (size_t)(bm + _row) * lda + _k0 + _cj * 4; \
        else if (_tile == 1) _src = Alo + (size_t)(bm + _row) * lda + _k0 + _cj * 4; \
        else {                                                                \
            int _ok = (bn + _row < Brows);                                    \
            const float* _b = (_tile == 2) ? Bhi : Blo;                       \
            _src = _ok ? (_b + (size_t)(bn + _row) * ldb + _k0 + _cj * 4) : _b; \
            _sz = _ok ? 16 : 0;                                               \
        }                                                                     \
        asm volatile("cp.async.cg.shared.global [%0], [%1], 16, %2;"          \
                     :: "r"(_dst), "l"(_src), "r"(_sz));                      \
    }                                                                         \
    asm volatile("cp.async.commit_group;" ::: "memory");                      \
} while (0)

    LOAD_TILE(0, 0);

    for (int kt = 0; kt < niter; kt++) {
        const int buf = kt & 1;
        if (kt + 1 < niter) {
            LOAD_TILE(buf ^ 1, kt + 1);
            asm volatile("cp.async.wait_group 1;" ::: "memory");
        } else {
            asm volatile("cp.async.wait_group 0;" ::: "memory");
        }
        __syncthreads();

        const float* ahs = sm + buf * 10240;
        const float* als = ahs + 2560;
        const float* bhs = ahs + 5120;
        const float* bls = ahs + 7680;

#pragma unroll
        for (int ks = 0; ks < 2; ks++) {
            const int r0 = wm * 64 + (lane >> 2);
            const int c0 = ks * 8 + (lane & 3);
            const int n0 = wn * 32 + (lane >> 2);

            uint32_t ah[4][4], bh[4][2];
#pragma unroll
            for (int mi = 0; mi < 4; mi++) {
                ah[mi][0] = __float_as_uint(ahs[(r0 + mi * 16) * 20 + c0]);
                ah[mi][1] = __float_as_uint(ahs[(r0 + mi * 16 + 8) * 20 + c0]);
                ah[mi][2] = __float_as_uint(ahs[(r0 + mi * 16) * 20 + c0 + 4]);
                ah[mi][3] = __float_as_uint(ahs[(r0 + mi * 16 + 8) * 20 + c0 + 4]);
            }
#pragma unroll
            for (int ni = 0; ni < 4; ni++) {
                bh[ni][0] = __float_as_uint(bhs[(n0 + ni * 8) * 20 + c0]);
                bh[ni][1] = __float_as_uint(bhs[(n0 + ni * 8) * 20 + c0 + 4]);
            }
#pragma unroll
            for (int mi = 0; mi < 4; mi++)
#pragma unroll
                for (int ni = 0; ni < 4; ni++)
                    mma_tf32(acc[mi][ni], ah[mi], bh[ni]);

            {
                uint32_t al[4][4];
#pragma unroll
                for (int mi = 0; mi < 4; mi++) {
                    al[mi][0] = __float_as_uint(als[(r0 + mi * 16) * 20 + c0]);
                    al[mi][1] = __float_as_uint(als[(r0 + mi * 16 + 8) * 20 + c0]);
                    al[mi][2] = __float_as_uint(als[(r0 + mi * 16) * 20 + c0 + 4]);
                    al[mi][3] = __float_as_uint(als[(r0 + mi * 16 + 8) * 20 + c0 + 4]);
                }
#pragma unroll
                for (int mi = 0; mi < 4; mi++)
#pragma unroll
                    for (int ni = 0; ni < 4; ni++)
                        mma_tf32(acc[mi][ni], al[mi], bh[ni]);
            }
            {
                uint32_t bl[4][2];
#pragma unroll
                for (int ni = 0; ni < 4; ni++) {
                    bl[ni][0] = __float_as_uint(bls[(n0 + ni * 8) * 20 + c0]);
                    bl[ni][1] = __float_as_uint(bls[(n0 + ni * 8) * 20 + c0 + 4]);
                }
#pragma unroll
                for (int mi = 0; mi < 4; mi++)
#pragma unroll
                    for (int ni = 0; ni < 4; ni++)
                        mma_tf32(acc[mi][ni], ah[mi], bl[ni]);
            }
        }
        __syncthreads();
    }
#undef LOAD_TILE

#pragma unroll
    for (int mi = 0; mi < 4; mi++)
#pragma unroll
        for (int ni = 0; ni < 4; ni++)
#pragma unroll
            for (int e = 0; e < 4; e++) {
                int m = bm + wm * 64 + mi * 16 + (lane >> 2) + ((e >= 2) ? 8 : 0);
                int n = bn + wn * 32 + ni * 8 + 2 * (lane & 3) + (e & 1);
                if (n >= Nreal) continue;
                float v = acc[mi][ni][e];
                if (bias)  v += bias[n];
                if (bias2) v += bias2[n];
                if (outLo) {
                    v = fmaxf(v, 0.0f);
                    float hi = tf32r(v);
                    outHi[(size_t)m * ldOut + n] = hi;
                    outLo[(size_t)m * ldOut + n] = v - hi;
                } else {
                    outHi[(size_t)m * ldOut + n] = v;
                }
            }
}

// ---------- prep kernels ----------
__global__ void build_A1(const float* __restrict__ s0, const float* __restrict__ s1,
                         const float* __restrict__ s2, const int* __restrict__ epPtr,
                         float* __restrict__ Ahi, float* __restrict__ Alo)
{
    int k = blockIdx.x * 256 + threadIdx.x;
    int m = blockIdx.y;
    if (k >= 9248) return;
    float v = 0.0f;
    if (k < 4608)       v = s0[(size_t)m * 4608 + k];
    else if (k < 9216)  v = s1[(size_t)m * 4608 + (k - 4608)];
    else if (k < 9224)  v = s2[m * 8 + (k - 9216)];
    else if (k == 9224) v = epPtr ? (float)(*epPtr) : 0.0f;
    float hi = tf32r(v);
    size_t b = (size_t)m * 9248 + k;
    Ahi[b] = hi; Alo[b] = v - hi;
}

__global__ void tsplit(const float* __restrict__ W, int K, int N,
                       float* __restrict__ outHi, float* __restrict__ outLo, int Kpad)
{
    __shared__ float t[32][33];
    int kb = blockIdx.x * 32, nb = blockIdx.y * 32;
    int tx = threadIdx.x, ty = threadIdx.y;
#pragma unroll
    for (int r = 0; r < 4; r++) {
        int k = kb + ty + r * 8, n = nb + tx;
        t[ty + r * 8][tx] = (k < K && n < N) ? W[(size_t)k * N + n] : 0.0f;
    }
    __syncthreads();
#pragma unroll
    for (int r = 0; r < 4; r++) {
        int n = nb + ty + r * 8, k = kb + tx;
        float v = t[tx][ty + r * 8];
        float hi = tf32r(v);
        size_t b = (size_t)n * Kpad + k;
        outHi[b] = hi; outLo[b] = v - hi;
    }
}

__global__ void split_lstm(const float* __restrict__ Wih, const float* __restrict__ Whh,
                           float* __restrict__ outHi, float* __restrict__ outLo)
{
    int idx = blockIdx.x * 256 + threadIdx.x;
    if (idx >= 2048 * 512) return;
    int n = idx >> 9, k = idx & 511;
    float a = Wih[idx], c = Whh[idx];
    float ah = tf32r(a), ch = tf32r(c);
    size_t b = (size_t)n * 1024;
    outHi[b + k] = ah;       outHi[b + 512 + k] = ch;
    outLo[b + k] = a - ah;   outLo[b + 512 + k] = c - ch;
}

__global__ void h0split(const float* __restrict__ h0,
                        float* __restrict__ ALhi, float* __restrict__ ALlo)
{
    int idx = blockIdx.x * 256 + threadIdx.x;
    if (idx >= NB * 512) return;
    int m = idx >> 9, c = idx & 511;
    float v = h0[idx];
    float hi = tf32r(v);
    size_t b = (size_t)m * 1024 + 512 + c;
    ALhi[b] = hi; ALlo[b] = v - hi;
}

__global__ void lstm_kernel(const float* __restrict__ gates,
                            const float* __restrict__ c0,
                            float* __restrict__ zhi, float* __restrict__ zlo)
{
    int i = blockIdx.x * blockDim.x + threadIdx.x;
    if (i >= NB * 512) return;
    int m = i >> 9, c = i & 511;
    const float* gr = gates + (size_t)m * 2048;
    float gi = gr[c], gf = gr[512 + c], gg = gr[1024 + c], go = gr[1536 + c];
    float si = 1.0f / (1.0f + expf(-gi));
    float sf = 1.0f / (1.0f + expf(-gf));
    float so = 1.0f / (1.0f + expf(-go));
    float cc = sf * c0[i] + si * tanhf(gg);
    float z = so * tanhf(cc);
    float hi = tf32r(z);
    size_t b = (size_t)m * 544 + c;
    zhi[b] = hi; zlo[b] = z - hi;
}

__global__ void sample_kernel(const float* __restrict__ logits,
                              float* __restrict__ zinHi, float* __restrict__ zinLo,
                              float* __restrict__ outAction,
                              float* __restrict__ lpAcc,
                              float* __restrict__ entAcc,
                              uint32_t sk0, uint32_t sk1, int head)
{
    int warp = (blockIdx.x * blockDim.x + threadIdx.x) >> 5;
    int lane = threadIdx.x & 31;
    if (warp >= NB) return;
    int r = warp;

    float x0 = logits[r * 64 + lane];
    float x1 = logits[r * 64 + 32 + lane];

    float mx = fmaxf(x0, x1);
#pragma unroll
    for (int o = 16; o; o >>= 1) mx = fmaxf(mx, __shfl_xor_sync(0xffffffffu, mx, o));
    float s = expf(x0 - mx) + expf(x1 - mx);
#pragma unroll
    for (int o = 16; o; o >>= 1) s += __shfl_xor_sync(0xffffffffu, s, o);
    float lse = mx + logf(s);

    float t = expf(x0 - lse) * (lse - x0) + expf(x1 - lse) * (lse - x1);
#pragma unroll
    for (int o = 16; o; o >>= 1) t += __shfl_xor_sync(0xffffffffu, t, o);

    float g0 = gumbel_for(sk0, sk1, (uint32_t)(r * 64 + lane));
    float g1 = gumbel_for(sk0, sk1, (uint32_t)(r * 64 + 32 + lane));
    float ya = x0 + g0, yb = x1 + g1;
    float y; int idx;
    if (ya >= yb) { y = ya; idx = lane; } else { y = yb; idx = lane + 32; }
#pragma unroll
    for (int o = 16; o; o >>= 1) {
        float oy = __shfl_xor_sync(0xffffffffu, y, o);
        int   oi = __shfl_xor_sync(0xffffffffu, idx, o);
        if (oy > y || (oy == y && oi < idx)) { y = oy; idx = oi; }
    }
    int src = idx & 31;
    float v0 = __shfl_sync(0xffffffffu, x0, src);
    float v1 = __shfl_sync(0xffffffffu, x1, src);
    float xw = (idx < 32) ? v0 : v1;

    if (lane == 0) {
        float a = (float)idx;
        size_t b = (size_t)r * 544 + 512;
        zinHi[b] = a;
        zinLo[b] = 0.0f;
        outAction[r * 8 + head] = a;
        lpAcc[r] += xw - lse;
        entAcc[r] += t;
    }
}

__global__ void init_kernel(float* __restrict__ lp, float* __restrict__ ent)
{
    int i = blockIdx.x * blockDim.x + threadIdx.x;
    if (i < NB) { lp[i] = 0.0f; ent[i] = 0.0f; }
}

__global__ void reduce_ent(const float* __restrict__ ent, float* __restrict__ out)
{
    __shared__ float sm[256];
    float s = 0.0f;
    for (int i = threadIdx.x; i < NB; i += 256) s += ent[i];
    sm[threadIdx.x] = s;
    __syncthreads();
    for (int o = 128; o; o >>= 1) {
        if (threadIdx.x < o) sm[threadIdx.x] += sm[threadIdx.x + o];
        __syncthreads();
    }
    if (threadIdx.x == 0) out[0] = sm[0];
}

// ---------- host launcher ----------
extern "C" void kernel_launch(void* const* d_in, const int* in_sizes, int n_in,
                              void* d_out, int out_size)
{
    const float* actual    = (const float*)d_in[0];
    const float* objective = (const float*)d_in[1];
    const float* last      = (const float*)d_in[2];

    int base = 4;
    const int* epPtr = nullptr;
    if (in_sizes[3] == 1) epPtr = (const int*)d_in[3];
    else base = 3;

    const float* W1  = (const float*)d_in[base + 0];
    const float* b1  = (const float*)d_in[base + 1];
    const float* W2  = (const float*)d_in[base + 2];
    const float* b2  = (const float*)d_in[base + 3];
    const float* W3  = (const float*)d_in[base + 4];
    const float* b3  = (const float*)d_in[base + 5];
    const float* Wih = (const float*)d_in[base + 6];
    const float* Whh = (const float*)d_in[base + 7];
    const float* bih = (const float*)d_in[base + 8];
    const float* bhh = (const float*)d_in[base + 9];
    const float* h0  = (const float*)d_in[base + 10];
    const float* c0  = (const float*)d_in[base + 11];
    const float* dW1 = (const float*)d_in[base + 12];
    const float* db1 = (const float*)d_in[base + 13];

    const float* headW[8];
    const float* headb[8];
    const float* dWo;
    const float* dbo;
    if (n_in >= base + 32) {
        for (int i = 0; i < 8; i++) {
            headW[i] = (const float*)d_in[base + 14 + i];
            headb[i] = (const float*)d_in[base + 22 + i];
        }
        dWo = (const float*)d_in[base + 30];
        dbo = (const float*)d_in[base + 31];
    } else {
        const float* hw = (const float*)d_in[base + 14];
        const float* hb = (const float*)d_in[base + 15];
        for (int i = 0; i < 8; i++) {
            headW[i] = hw + (size_t)i * 256 * 64;
            headb[i] = hb + (size_t)i * 64;
        }
        dWo = (const float*)d_in[base + 16];
        dbo = (const float*)d_in[base + 17];
    }
    const int D1 = in_sizes[base + 1];  // 3518
    const int D2 = in_sizes[base + 3];  // 1342

    float* sc = nullptr;
    cudaGetSymbolAddress((void**)&sc, g_scratch);
    float* a1hi = sc + A1HI;  float* a1lo = sc + A1LO;
    float* b1hi = sc + B1HI;  float* b1lo = sc + B1LO;
    float* a2hi = sc + A2HI;  float* a2lo = sc + A2LO;
    float* b2hi = sc + B2HI;  float* b2lo = sc + B2LO;
    float* a3hi = sc + A3HI;  float* a3lo = sc + A3LO;
    float* b3hi = sc + B3HI;  float* b3lo = sc + B3LO;
    float* alhi = sc + ALHI;  float* allo = sc + ALLO;
    float* blhi = sc + BLHI;  float* bllo = sc + BLLO;
    float* gates = sc + GOFF;
    float* zahi = sc + ZAHI;  float* zalo = sc + ZALO;
    float* zbhi = sc + ZBHI;  float* zblo = sc + ZBLO;
    float* z1hi = sc + Z1HI;  float* z1lo = sc + Z1LO;
    float* bd1hi = sc + BD1HI; float* bd1lo = sc + BD1LO;
    float* bdohi = sc + BDOHI; float* bdolo = sc + BDOLO;
    float* bhhi = sc + BHHI;  float* bhlo = sc + BHLO;
    float* logb = sc + LOGO;
    float* entb = sc + ENTO;

    float* out  = (float*)d_out;
    float* lp   = out + NB * 8 + 1;
    float* entO = out + NB * 8;

    uint32_t k0 = 0u, k1 = 42u, sk0[8], sk1[8];
    for (int t = 0; t < 8; t++) {
        uint32_t n0, n1, s0, s1;
        threefry2x32(k0, k1, 0u, 0u, &n0, &n1);
        threefry2x32(k0, k1, 0u, 1u, &s0, &s1);
        sk0[t] = s0; sk1[t] = s1;
        k0 = n0; k1 = n1;
    }

    const int SMEM = 2 * 40960;  // 81920 B
    cudaFuncSetAttribute(mma_gemm, cudaFuncAttributeMaxDynamicSharedMemorySize, SMEM);

    dim3 blk(256);
    dim3 tsb(32, 8);

    init_kernel<<<(NB + 255) / 256, blk>>>(lp, entb);

    // weight prep (hi/lo)
    tsplit<<<dim3(289, 110), tsb>>>(W1, 9225, D1, b1hi, b1lo, 9248);
    tsplit<<<dim3(110, 42),  tsb>>>(W2, D1, D2, b2hi, b2lo, 3520);
    tsplit<<<dim3(42, 16),   tsb>>>(W3, D2, 512, b3hi, b3lo, 1344);
    split_lstm<<<(2048 * 512 + 255) / 256, blk>>>(Wih, Whh, blhi, bllo);
    h0split<<<(NB * 512 + 255) / 256, blk>>>(h0, alhi, allo);
    tsplit<<<dim3(17, 8),  tsb>>>(dW1, 512, 256, bd1hi, bd1lo, 544);
    tsplit<<<dim3(17, 16), tsb>>>(dWo, 513, 512, bdohi, bdolo, 544);
    for (int t = 0; t < 8; t++)
        tsplit<<<dim3(8, 2), tsb>>>(headW[t], 256, 64,
                                    bhhi + (size_t)t * 16384, bhlo + (size_t)t * 16384, 256);
    build_A1<<<dim3(37, 4096), blk>>>(actual, objective, last, epPtr, a1hi, a1lo);

    // encoder
    mma_gemm<<<dim3(28, 32), blk, SMEM>>>(a1hi, a1lo, 9248, b1hi, b1lo, 9248,
        3520, 9248, b1, nullptr, a2hi, a2lo, 3520, D1);
    mma_gemm<<<dim3(11, 32), blk, SMEM>>>(a2hi, a2lo, 3520, b2hi, b2lo, 3520,
        1344, 3520, b2, nullptr, a3hi, a3lo, 1344, D2);
    mma_gemm<<<dim3(4, 32), blk, SMEM>>>(a3hi, a3lo, 1344, b3hi, b3lo, 1344,
        512, 1344, b3, nullptr, alhi, allo, 1024, 512);

    // LSTM
    mma_gemm<<<dim3(16, 32), blk, SMEM>>>(alhi, allo, 1024, blhi, bllo, 1024,
        2048, 1024, bih, bhh, gates, nullptr, 2048, 2048);
    lstm_kernel<<<(NB * 512 + 255) / 256, blk>>>(gates, c0, zahi, zalo);

    // decoder
    for (int t = 0; t < 8; t++) {
        float* zihi = (t & 1) ? zbhi : zahi;
        float* zilo = (t & 1) ? zblo : zalo;
        float* zohi = (t & 1) ? zahi : zbhi;
        float* zolo = (t & 1) ? zalo : zblo;
        mma_gemm<<<dim3(2, 32), blk, SMEM>>>(zihi, zilo, 544, bd1hi, bd1lo, 544,
            256, 544, db1, nullptr, z1hi, z1lo, 256, 256);
        mma_gemm<<<dim3(1, 32), blk, SMEM>>>(z1hi, z1lo, 256,
            bhhi + (size_t)t * 16384, bhlo + (size_t)t * 16384, 256,
            64, 256, headb[t], nullptr, logb, nullptr, 64, 64);
        sample_kernel<<<NB / 8, blk>>>(logb, zihi, zilo, out, lp, entb, sk0[t], sk1[t], t);
        mma_gemm<<<dim3(4, 32), blk, SMEM>>>(zihi, zilo, 544, bdohi, bdolo, 544,
            512, 544, dbo, nullptr, zohi, zolo, 544, 512);
    }

    reduce_ent<<<1, blk>>>(entb, entO);
}

// round 9
// speedup vs baseline: 2.2999x; 1.9189x over previous
#include <cuda_runtime.h>
#include <cuda_fp16.h>
#include <stdint.h>
#include <math.h>

#define NB 4096

__device__ __half g_h[216240128];
__device__ float  g_f[8655872];

#define A1HI 0u
#define A1LO 37879808u
#define B1HI 75759616u
#define B1LO 108312576u
#define A2HI 140865536u
#define A2LO 155283456u
#define B2HI 169701376u
#define B2LO 174432256u
#define A3HI 179163136u
#define A3LO 184668160u
#define B3HI 190173184u
#define B3LO 190861312u
#define ALHI 191549440u
#define ALLO 195743744u
#define BLHI 199938048u
#define BLLO 202035200u
#define ZAHI 204132352u
#define ZALO 206360576u
#define ZBHI 208588800u
#define ZBLO 210817024u
#define Z1HI 213045248u
#define Z1LO 214093824u
#define BD1HI 215142400u
#define BD1LO 215281664u
#define BDOHI 215420928u
#define BDOLO 215699456u
#define BHHI 215977984u
#define BHLO 216109056u

#define GOFF 0u
#define LOGO 8388608u
#define ENTO 8650752u

__device__ __forceinline__ uint32_t smem_u32(const void* p) {
    uint32_t a;
    asm("{ .reg .u64 t; cvta.to.shared.u64 t, %1; cvt.u32.u64 %0, t; }" : "=r"(a) : "l"(p));
    return a;
}

// ---------- threefry (JAX partitionable) ----------
__host__ __device__ __forceinline__ void threefry2x32(
    uint32_t k0, uint32_t k1, uint32_t x0, uint32_t x1, uint32_t* o0, uint32_t* o1)
{
    uint32_t ks0 = k0, ks1 = k1, ks2 = 0x1BD11BDAu ^ k0 ^ k1;
    x0 += ks0; x1 += ks1;
#define TF_ROUND(r) do { x0 += x1; x1 = (x1 << (r)) | (x1 >> (32 - (r))); x1 ^= x0; } while (0)
    TF_ROUND(13); TF_ROUND(15); TF_ROUND(26); TF_ROUND(6);
    x0 += ks1; x1 += ks2 + 1u;
    TF_ROUND(17); TF_ROUND(29); TF_ROUND(16); TF_ROUND(24);
    x0 += ks2; x1 += ks0 + 2u;
    TF_ROUND(13); TF_ROUND(15); TF_ROUND(26); TF_ROUND(6);
    x0 += ks0; x1 += ks1 + 3u;
    TF_ROUND(17); TF_ROUND(29); TF_ROUND(16); TF_ROUND(24);
    x0 += ks1; x1 += ks2 + 4u;
    TF_ROUND(13); TF_ROUND(15); TF_ROUND(26); TF_ROUND(6);
    x0 += ks2; x1 += ks0 + 5u;
#undef TF_ROUND
    *o0 = x0; *o1 = x1;
}
__device__ __forceinline__ float gumbel_for(uint32_t k0, uint32_t k1, uint32_t j)
{
    uint32_t o0, o1;
    threefry2x32(k0, k1, 0u, j, &o0, &o1);
    uint32_t bits = o0 ^ o1;
    uint32_t fb = (bits >> 9) | 0x3f800000u;
    float f = __uint_as_float(fb) - 1.0f;
    if (f == 0.0f) f = 1.1754943508222875e-38f;
    return -logf(-logf(f));
}

__device__ __forceinline__ void mma_f16(float* c, const uint32_t* a, const uint32_t* b)
{
    asm volatile(
        "mma.sync.aligned.m16n8k16.row.col.f32.f16.f16.f32 "
        "{%0,%1,%2,%3}, {%4,%5,%6,%7}, {%8,%9}, {%0,%1,%2,%3};"
        : "+f"(c[0]), "+f"(c[1]), "+f"(c[2]), "+f"(c[3])
        : "r"(a[0]), "r"(a[1]), "r"(a[2]), "r"(a[3]), "r"(b[0]), "r"(b[1]));
}

// ==================================================================
// fused 3xFP16 GEMM: per 32-wide k-chunk load Ahi/Alo/Bhi/Blo once,
// accumulate hi*hi + lo*hi + hi*lo in fp32.
// 128x128 tile, 256 thr, 2-stage cp.async, 2 CTAs/SM.
// tile = 128 rows x 40 halves (80 B pitch, 64 B data); stage = 40960 B
// ==================================================================
__global__ void __launch_bounds__(256, 2)
mma_gemm(const __half* __restrict__ Ahi, const __half* __restrict__ Alo, int lda,
         const __half* __restrict__ Bhi, const __half* __restrict__ Blo, int ldb,
         int Brows, int Kpad,
         const float* __restrict__ bias, const float* __restrict__ bias2,
         __half* __restrict__ outHi, __half* __restrict__ outLo,
         float* __restrict__ outF, int ldOut, int Nreal)
{
    extern __shared__ __half smh[];
    const int tid  = threadIdx.x;
    const int bm   = blockIdx.y * 128;
    const int bn   = blockIdx.x * 128;
    const int lane = tid & 31;
    const int wid  = tid >> 5;
    const int wm   = wid >> 2;
    const int wn   = wid & 3;
    const int niter = Kpad >> 5;

    const uint32_t base = smem_u32(smh);

    float acc[4][4][4];
#pragma unroll
    for (int i = 0; i < 4; i++)
#pragma unroll
        for (int j = 0; j < 4; j++)
#pragma unroll
            for (int e = 0; e < 4; e++) acc[i][j][e] = 0.0f;

#define LOAD_TILE(buf, kt) do {                                               \
    int _k0 = (kt) * 32;                                                      \
    _Pragma("unroll")                                                         \
    for (int _i = 0; _i < 8; _i++) {                                          \
        int _idx = tid + _i * 256;                                            \
        int _tile = _idx >> 9;                                                \
        int _rem  = _idx & 511;                                               \
        int _row  = _rem >> 2, _cj = _rem & 3;                                \
        uint32_t _dst = base + (buf) * 40960u + _tile * 10240u + _row * 80u + _cj * 16u; \
        const __half* _src;                                                   \
        int _sz = 16;                                                         \
        if (_tile == 0)      _src = Ahi + (size_t)(bm + _row) * lda + _k0 + _cj * 8; \
        else if (_tile == 1) _src = Alo + (size_t)(bm + _row) * lda + _k0 + _cj * 8; \
        else {                                                                \
            int _ok = (bn + _row < Brows);                                    \
            const __half* _b = (_tile == 2) ? Bhi : Blo;                      \
            _src = _ok ? (_b + (size_t)(bn + _row) * ldb + _k0 + _cj * 8) : _b; \
            _sz = _ok ? 16 : 0;                                               \
        }                                                                     \
        asm volatile("cp.async.cg.shared.global [%0], [%1], 16, %2;"          \
                     :: "r"(_dst), "l"(_src), "r"(_sz));                      \
    }                                                                         \
    asm volatile("cp.async.commit_group;" ::: "memory");                      \
} while (0)

    LOAD_TILE(0, 0);

    for (int kt = 0; kt < niter; kt++) {
        const int buf = kt & 1;
        if (kt + 1 < niter) {
            LOAD_TILE(buf ^ 1, kt + 1);
            asm volatile("cp.async.wait_group 1;" ::: "memory");
        } else {
            asm volatile("cp.async.wait_group 0;" ::: "memory");
        }
        __syncthreads();

        const __half* ahs = smh + buf * 20480;
        const __half* als = ahs + 5120;
        const __half* bhs = ahs + 10240;
        const __half* bls = ahs + 15360;

#pragma unroll
        for (int ks = 0; ks < 2; ks++) {
            const int r0 = wm * 64 + (lane >> 2);
            const int n0 = wn * 32 + (lane >> 2);
            const int c0 = ks * 16 + (lane & 3) * 2;

            uint32_t ah[4][4], bh[4][2];
#pragma unroll
            for (int mi = 0; mi < 4; mi++) {
                ah[mi][0] = *(const uint32_t*)(ahs + (r0 + mi * 16) * 40 + c0);
                ah[mi][1] = *(const uint32_t*)(ahs + (r0 + mi * 16 + 8) * 40 + c0);
                ah[mi][2] = *(const uint32_t*)(ahs + (r0 + mi * 16) * 40 + c0 + 8);
                ah[mi][3] = *(const uint32_t*)(ahs + (r0 + mi * 16 + 8) * 40 + c0 + 8);
            }
#pragma unroll
            for (int ni = 0; ni < 4; ni++) {
                bh[ni][0] = *(const uint32_t*)(bhs + (n0 + ni * 8) * 40 + c0);
                bh[ni][1] = *(const uint32_t*)(bhs + (n0 + ni * 8) * 40 + c0 + 8);
            }
#pragma unroll
            for (int mi = 0; mi < 4; mi++)
#pragma unroll
                for (int ni = 0; ni < 4; ni++)
                    mma_f16(acc[mi][ni], ah[mi], bh[ni]);

            {
                uint32_t al[4][4];
#pragma unroll
                for (int mi = 0; mi < 4; mi++) {
                    al[mi][0] = *(const uint32_t*)(als + (r0 + mi * 16) * 40 + c0);
                    al[mi][1] = *(const uint32_t*)(als + (r0 + mi * 16 + 8) * 40 + c0);
                    al[mi][2] = *(const uint32_t*)(als + (r0 + mi * 16) * 40 + c0 + 8);
                    al[mi][3] = *(const uint32_t*)(als + (r0 + mi * 16 + 8) * 40 + c0 + 8);
                }
#pragma unroll
                for (int mi = 0; mi < 4; mi++)
#pragma unroll
                    for (int ni = 0; ni < 4; ni++)
                        mma_f16(acc[mi][ni], al[mi], bh[ni]);
            }
            {
                uint32_t bl[4][2];
#pragma unroll
                for (int ni = 0; ni < 4; ni++) {
                    bl[ni][0] = *(const uint32_t*)(bls + (n0 + ni * 8) * 40 + c0);
                    bl[ni][1] = *(const uint32_t*)(bls + (n0 + ni * 8) * 40 + c0 + 8);
                }
#pragma unroll
                for (int mi = 0; mi < 4; mi++)
#pragma unroll
                    for (int ni = 0; ni < 4; ni++)
                        mma_f16(acc[mi][ni], ah[mi], bl[ni]);
            }
        }
        __syncthreads();
    }
#undef LOAD_TILE

#pragma unroll
    for (int mi = 0; mi < 4; mi++)
#pragma unroll
        for (int ni = 0; ni < 4; ni++)
#pragma unroll
            for (int e = 0; e < 4; e++) {
                int m = bm + wm * 64 + mi * 16 + (lane >> 2) + ((e >= 2) ? 8 : 0);
                int n = bn + wn * 32 + ni * 8 + 2 * (lane & 3) + (e & 1);
                if (n >= Nreal) continue;
                float v = acc[mi][ni][e];
                if (bias)  v += bias[n];
                if (bias2) v += bias2[n];
                if (outF) {
                    outF[(size_t)m * ldOut + n] = v;
                } else {
                    v = fmaxf(v, 0.0f);
                    __half hi = __float2half_rn(v);
                    outHi[(size_t)m * ldOut + n] = hi;
                    outLo[(size_t)m * ldOut + n] = __float2half_rn(v - __half2float(hi));
                }
            }
}

// ---------- prep kernels ----------
__device__ __forceinline__ void hsplit(float v, __half* hi, __half* lo)
{
    __half h = __float2half_rn(v);
    *hi = h; *lo = __float2half_rn(v - __half2float(h));
}

__global__ void build_A1(const float* __restrict__ s0, const float* __restrict__ s1,
                         const float* __restrict__ s2, const int* __restrict__ epPtr,
                         __half* __restrict__ Ahi, __half* __restrict__ Alo)
{
    int k = blockIdx.x * 256 + threadIdx.x;
    int m = blockIdx.y;
    if (k >= 9248) return;
    float v = 0.0f;
    if (k < 4608)       v = s0[(size_t)m * 4608 + k];
    else if (k < 9216)  v = s1[(size_t)m * 4608 + (k - 4608)];
    else if (k < 9224)  v = s2[m * 8 + (k - 9216)];
    else if (k == 9224) v = epPtr ? (float)(*epPtr) : 0.0f;
    size_t b = (size_t)m * 9248 + k;
    hsplit(v, &Ahi[b], &Alo[b]);
}

__global__ void tsplit(const float* __restrict__ W, int K, int N,
                       __half* __restrict__ outHi, __half* __restrict__ outLo, int Kpad)
{
    __shared__ float t[32][33];
    int kb = blockIdx.x * 32, nb = blockIdx.y * 32;
    int tx = threadIdx.x, ty = threadIdx.y;
#pragma unroll
    for (int r = 0; r < 4; r++) {
        int k = kb + ty + r * 8, n = nb + tx;
        t[ty + r * 8][tx] = (k < K && n < N) ? W[(size_t)k * N + n] : 0.0f;
    }
    __syncthreads();
#pragma unroll
    for (int r = 0; r < 4; r++) {
        int n = nb + ty + r * 8, k = kb + tx;
        size_t b = (size_t)n * Kpad + k;
        hsplit(t[tx][ty + r * 8], &outHi[b], &outLo[b]);
    }
}

__global__ void split_lstm(const float* __restrict__ Wih, const float* __restrict__ Whh,
                           __half* __restrict__ outHi, __half* __restrict__ outLo)
{
    int idx = blockIdx.x * 256 + threadIdx.x;
    if (idx >= 2048 * 512) return;
    int n = idx >> 9, k = idx & 511;
    size_t b = (size_t)n * 1024;
    hsplit(Wih[idx], &outHi[b + k], &outLo[b + k]);
    hsplit(Whh[idx], &outHi[b + 512 + k], &outLo[b + 512 + k]);
}

__global__ void h0split(const float* __restrict__ h0,
                        __half* __restrict__ ALhi, __half* __restrict__ ALlo)
{
    int idx = blockIdx.x * 256 + threadIdx.x;
    if (idx >= NB * 512) return;
    int m = idx >> 9, c = idx & 511;
    size_t b = (size_t)m * 1024 + 512 + c;
    hsplit(h0[idx], &ALhi[b], &ALlo[b]);
}

__global__ void lstm_kernel(const float* __restrict__ gates,
                            const float* __restrict__ c0,
                            __half* __restrict__ zhi, __half* __restrict__ zlo)
{
    int i = blockIdx.x * blockDim.x + threadIdx.x;
    if (i >= NB * 512) return;
    int m = i >> 9, c = i & 511;
    const float* gr = gates + (size_t)m * 2048;
    float gi = gr[c], gf = gr[512 + c], gg = gr[1024 + c], go = gr[1536 + c];
    float si = 1.0f / (1.0f + expf(-gi));
    float sf = 1.0f / (1.0f + expf(-gf));
    float so = 1.0f / (1.0f + expf(-go));
    float cc = sf * c0[i] + si * tanhf(gg);
    float z = so * tanhf(cc);
    size_t b = (size_t)m * 544 + c;
    hsplit(z, &zhi[b], &zlo[b]);
}

__global__ void sample_kernel(const float* __restrict__ logits,
                              __half* __restrict__ zinHi, __half* __restrict__ zinLo,
                              float* __restrict__ outAction,
                              float* __restrict__ lpAcc,
                              float* __restrict__ entAcc,
                              uint32_t sk0, uint32_t sk1, int head)
{
    int warp = (blockIdx.x * blockDim.x + threadIdx.x) >> 5;
    int lane = threadIdx.x & 31;
    if (warp >= NB) return;
    int r = warp;

    float x0 = logits[r * 64 + lane];
    float x1 = logits[r * 64 + 32 + lane];

    float mx = fmaxf(x0, x1);
#pragma unroll
    for (int o = 16; o; o >>= 1) mx = fmaxf(mx, __shfl_xor_sync(0xffffffffu, mx, o));
    float s = expf(x0 - mx) + expf(x1 - mx);
#pragma unroll
    for (int o = 16; o; o >>= 1) s += __shfl_xor_sync(0xffffffffu, s, o);
    float lse = mx + logf(s);

    float t = expf(x0 - lse) * (lse - x0) + expf(x1 - lse) * (lse - x1);
#pragma unroll
    for (int o = 16; o; o >>= 1) t += __shfl_xor_sync(0xffffffffu, t, o);

    float g0 = gumbel_for(sk0, sk1, (uint32_t)(r * 64 + lane));
    float g1 = gumbel_for(sk0, sk1, (uint32_t)(r * 64 + 32 + lane));
    float ya = x0 + g0, yb = x1 + g1;
    float y; int idx;
    if (ya >= yb) { y = ya; idx = lane; } else { y = yb; idx = lane + 32; }
#pragma unroll
    for (int o = 16; o; o >>= 1) {
        float oy = __shfl_xor_sync(0xffffffffu, y, o);
        int   oi = __shfl_xor_sync(0xffffffffu, idx, o);
        if (oy > y || (oy == y && oi < idx)) { y = oy; idx = oi; }
    }
    int src = idx & 31;
    float v0 = __shfl_sync(0xffffffffu, x0, src);
    float v1 = __shfl_sync(0xffffffffu, x1, src);
    float xw = (idx < 32) ? v0 : v1;

    if (lane == 0) {
        float a = (float)idx;
        size_t b = (size_t)r * 544 + 512;
        zinHi[b] = __float2half_rn(a);   // <=63, exact in fp16
        zinLo[b] = __float2half_rn(0.0f);
        outAction[r * 8 + head] = a;
        lpAcc[r] += xw - lse;
        entAcc[r] += t;
    }
}

__global__ void init_kernel(float* __restrict__ lp, float* __restrict__ ent)
{
    int i = blockIdx.x * blockDim.x + threadIdx.x;
    if (i < NB) { lp[i] = 0.0f; ent[i] = 0.0f; }
}

__global__ void reduce_ent(const float* __restrict__ ent, float* __restrict__ out)
{
    __shared__ float sm[256];
    float s = 0.0f;
    for (int i = threadIdx.x; i < NB; i += 256) s += ent[i];
    sm[threadIdx.x] = s;
    __syncthreads();
    for (int o = 128; o; o >>= 1) {
        if (threadIdx.x < o) sm[threadIdx.x] += sm[threadIdx.x + o];
        __syncthreads();
    }
    if (threadIdx.x == 0) out[0] = sm[0];
}

// ---------- host launcher ----------
extern "C" void kernel_launch(void* const* d_in, const int* in_sizes, int n_in,
                              void* d_out, int out_size)
{
    const float* actual    = (const float*)d_in[0];
    const float* objective = (const float*)d_in[1];
    const float* last      = (const float*)d_in[2];

    int base = 4;
    const int* epPtr = nullptr;
    if (in_sizes[3] == 1) epPtr = (const int*)d_in[3];
    else base = 3;

    const float* W1  = (const float*)d_in[base + 0];
    const float* b1  = (const float*)d_in[base + 1];
    const float* W2  = (const float*)d_in[base + 2];
    const float* b2  = (const float*)d_in[base + 3];
    const float* W3  = (const float*)d_in[base + 4];
    const float* b3  = (const float*)d_in[base + 5];
    const float* Wih = (const float*)d_in[base + 6];
    const float* Whh = (const float*)d_in[base + 7];
    const float* bih = (const float*)d_in[base + 8];
    const float* bhh = (const float*)d_in[base + 9];
    const float* h0  = (const float*)d_in[base + 10];
    const float* c0  = (const float*)d_in[base + 11];
    const float* dW1 = (const float*)d_in[base + 12];
    const float* db1 = (const float*)d_in[base + 13];

    const float* headW[8];
    const float* headb[8];
    const float* dWo;
    const float* dbo;
    if (n_in >= base + 32) {
        for (int i = 0; i < 8; i++) {
            headW[i] = (const float*)d_in[base + 14 + i];
            headb[i] = (const float*)d_in[base + 22 + i];
        }
        dWo = (const float*)d_in[base + 30];
        dbo = (const float*)d_in[base + 31];
    } else {
        const float* hw = (const float*)d_in[base + 14];
        const float* hb = (const float*)d_in[base + 15];
        for (int i = 0; i < 8; i++) {
            headW[i] = hw + (size_t)i * 256 * 64;
            headb[i] = hb + (size_t)i * 64;
        }
        dWo = (const float*)d_in[base + 16];
        dbo = (const float*)d_in[base + 17];
    }
    const int D1 = in_sizes[base + 1];  // 3518
    const int D2 = in_sizes[base + 3];  // 1342

    __half* hh = nullptr;
    float*  ff = nullptr;
    cudaGetSymbolAddress((void**)&hh, g_h);
    cudaGetSymbolAddress((void**)&ff, g_f);
    __half* a1hi = hh + A1HI;  __half* a1lo = hh + A1LO;
    __half* b1hi = hh + B1HI;  __half* b1lo = hh + B1LO;
    __half* a2hi = hh + A2HI;  __half* a2lo = hh + A2LO;
    __half* b2hi = hh + B2HI;  __half* b2lo = hh + B2LO;
    __half* a3hi = hh + A3HI;  __half* a3lo = hh + A3LO;
    __half* b3hi = hh + B3HI;  __half* b3lo = hh + B3LO;
    __half* alhi = hh + ALHI;  __half* allo = hh + ALLO;
    __half* blhi = hh + BLHI;  __half* bllo = hh + BLLO;
    __half* zahi = hh + ZAHI;  __half* zalo = hh + ZALO;
    __half* zbhi = hh + ZBHI;  __half* zblo = hh + ZBLO;
    __half* z1hi = hh + Z1HI;  __half* z1lo = hh + Z1LO;
    __half* bd1hi = hh + BD1HI; __half* bd1lo = hh + BD1LO;
    __half* bdohi = hh + BDOHI; __half* bdolo = hh + BDOLO;
    __half* bhhi = hh + BHHI;  __half* bhlo = hh + BHLO;
    float* gates = ff + GOFF;
    float* logb  = ff + LOGO;
    float* entb  = ff + ENTO;

    float* out  = (float*)d_out;
    float* lp   = out + NB * 8 + 1;
    float* entO = out + NB * 8;

    uint32_t k0 = 0u, k1 = 42u, sk0[8], sk1[8];
    for (int t = 0; t < 8; t++) {
        uint32_t n0, n1, s0, s1;
        threefry2x32(k0, k1, 0u, 0u, &n0, &n1);
        threefry2x32(k0, k1, 0u, 1u, &s0, &s1);
        sk0[t] = s0; sk1[t] = s1;
        k0 = n0; k1 = n1;
    }

    const int SMEM = 2 * 40960;  // 81920 B
    cudaFuncSetAttribute(mma_gemm, cudaFuncAttributeMaxDynamicSharedMemorySize, SMEM);

    dim3 blk(256);
    dim3 tsb(32, 8);

    init_kernel<<<(NB + 255) / 256, blk>>>(lp, entb);

    // weight prep (fp16 hi/lo)
    tsplit<<<dim3(289, 110), tsb>>>(W1, 9225, D1, b1hi, b1lo, 9248);
    tsplit<<<dim3(110, 42),  tsb>>>(W2, D1, D2, b2hi, b2lo, 3520);
    tsplit<<<dim3(42, 16),   tsb>>>(W3, D2, 512, b3hi, b3lo, 1344);
    split_lstm<<<(2048 * 512 + 255) / 256, blk>>>(Wih, Whh, blhi, bllo);
    h0split<<<(NB * 512 + 255) / 256, blk>>>(h0, alhi, allo);
    tsplit<<<dim3(17, 8),  tsb>>>(dW1, 512, 256, bd1hi, bd1lo, 544);
    tsplit<<<dim3(17, 16), tsb>>>(dWo, 513, 512, bdohi, bdolo, 544);
    for (int t = 0; t < 8; t++)
        tsplit<<<dim3(8, 2), tsb>>>(headW[t], 256, 64,
                                    bhhi + (size_t)t * 16384, bhlo + (size_t)t * 16384, 256);
    build_A1<<<dim3(37, 4096), blk>>>(actual, objective, last, epPtr, a1hi, a1lo);

    // encoder
    mma_gemm<<<dim3(28, 32), blk, SMEM>>>(a1hi, a1lo, 9248, b1hi, b1lo, 9248,
        3520, 9248, b1, nullptr, a2hi, a2lo, nullptr, 3520, D1);
    mma_gemm<<<dim3(11, 32), blk, SMEM>>>(a2hi, a2lo, 3520, b2hi, b2lo, 3520,
        1344, 3520, b2, nullptr, a3hi, a3lo, nullptr, 1344, D2);
    mma_gemm<<<dim3(4, 32), blk, SMEM>>>(a3hi, a3lo, 1344, b3hi, b3lo, 1344,
        512, 1344, b3, nullptr, alhi, allo, nullptr, 1024, 512);

    // LSTM (float store into gates)
    mma_gemm<<<dim3(16, 32), blk, SMEM>>>(alhi, allo, 1024, blhi, bllo, 1024,
        2048, 1024, bih, bhh, nullptr, nullptr, gates, 2048, 2048);
    lstm_kernel<<<(NB * 512 + 255) / 256, blk>>>(gates, c0, zahi, zalo);

    // decoder
    for (int t = 0; t < 8; t++) {
        __half* zihi = (t & 1) ? zbhi : zahi;
        __half* zilo = (t & 1) ? zblo : zalo;
        __half* zohi = (t & 1) ? zahi : zbhi;
        __half* zolo = (t & 1) ? zalo : zblo;
        mma_gemm<<<dim3(2, 32), blk, SMEM>>>(zihi, zilo, 544, bd1hi, bd1lo, 544,
            256, 544, db1, nullptr, z1hi, z1lo, nullptr, 256, 256);
        mma_gemm<<<dim3(1, 32), blk, SMEM>>>(z1hi, z1lo, 256,
            bhhi + (size_t)t * 16384, bhlo + (size_t)t * 16384, 256,
            64, 256, headb[t], nullptr, nullptr, nullptr, logb, 64, 64);
        sample_kernel<<<NB / 8, blk>>>(logb, zihi, zilo, out, lp, entb, sk0[t], sk1[t], t);
        mma_gemm<<<dim3(4, 32), blk, SMEM>>>(zihi, zilo, 544, bdohi, bdolo, 544,
            512, 544, dbo, nullptr, zohi, zolo, nullptr, 544, 512);
    }

    reduce_ent<<<1, blk>>>(entb, entO);
}